// round 1
// baseline (speedup 1.0000x reference)
#include <cuda_runtime.h>
#include <cuda_bf16.h>
#include <cstdio>

// ---------------------------------------------------------------------------
// Problem constants
// ---------------------------------------------------------------------------
#define SEQ    2048
#define BATCH  8
#define DMODEL 512
#define HEADS  8
#define DK     64
#define DFF    2048
#define TTOK   (SEQ * BATCH)          // 16384 tokens, t = s*BATCH + b

// ---------------------------------------------------------------------------
// Device scratch (static allocation; harness forbids cudaMalloc)
// ---------------------------------------------------------------------------
__device__ float g_Q   [TTOK * DMODEL];
__device__ float g_V   [TTOK * DMODEL];
__device__ float g_R   [TTOK * DMODEL];
__device__ float g_H   [TTOK * DMODEL];
__device__ float g_attn[TTOK * DMODEL];   // attention out, pre-Wo
__device__ float g_tmp [TTOK * DMODEL];   // proj / ff2 output
__device__ float g_x1  [TTOK * DMODEL];   // after first add+LN
__device__ float g_ff  [TTOK * DFF];      // ff hidden

// ---------------------------------------------------------------------------
// Generic SGEMM:  C[M,N] = A[M,K] @ W(+layout) + bias, optional ReLU
//   WT = true : W is (N,K) row-major,   C = A @ W^T   (Wq/Wv/Wr/Wo)
//   WT = false: W is (K,N) row-major,   C = A @ W     (Wf1/Wf2)
// Tiling: BM=BN=128, BK=8, 256 threads, 8x8 per thread.
// ---------------------------------------------------------------------------
template<bool WT, bool RELU>
__global__ void __launch_bounds__(256)
gemm_bias(const float* __restrict__ A, const float* __restrict__ W,
          const float* __restrict__ bias, float* __restrict__ C,
          int M, int N, int K)
{
    __shared__ float As[8][128];
    __shared__ float Bs[8][128];

    const int tid = threadIdx.x;
    const int bm  = blockIdx.y * 128;
    const int bn  = blockIdx.x * 128;
    const int ty  = tid >> 4;       // 0..15
    const int tx  = tid & 15;       // 0..15

    float acc[8][8] = {};

    const int a_row = tid >> 1;             // 0..127
    const int a_k   = (tid & 1) * 4;        // 0 or 4

    for (int k0 = 0; k0 < K; k0 += 8) {
        // --- A tile (transposed into As[k][m]) ---
        float4 av = *(const float4*)&A[(size_t)(bm + a_row) * K + k0 + a_k];
        As[a_k + 0][a_row] = av.x;
        As[a_k + 1][a_row] = av.y;
        As[a_k + 2][a_row] = av.z;
        As[a_k + 3][a_row] = av.w;
        // --- W tile into Bs[k][n] ---
        if (WT) {
            const int n  = tid >> 1;
            const int kq = (tid & 1) * 4;
            float4 wv = *(const float4*)&W[(size_t)(bn + n) * K + k0 + kq];
            Bs[kq + 0][n] = wv.x;
            Bs[kq + 1][n] = wv.y;
            Bs[kq + 2][n] = wv.z;
            Bs[kq + 3][n] = wv.w;
        } else {
            const int kk = tid >> 5;          // 0..7
            const int n4 = (tid & 31) * 4;    // 0..124
            *(float4*)&Bs[kk][n4] = *(const float4*)&W[(size_t)(k0 + kk) * N + bn + n4];
        }
        __syncthreads();

        #pragma unroll
        for (int k = 0; k < 8; k++) {
            float a[8], b[8];
            #pragma unroll
            for (int i = 0; i < 8; i++) a[i] = As[k][ty * 8 + i];
            #pragma unroll
            for (int j = 0; j < 8; j++) b[j] = Bs[k][tx * 8 + j];
            #pragma unroll
            for (int i = 0; i < 8; i++)
                #pragma unroll
                for (int j = 0; j < 8; j++)
                    acc[i][j] = fmaf(a[i], b[j], acc[i][j]);
        }
        __syncthreads();
    }

    #pragma unroll
    for (int i = 0; i < 8; i++) {
        const size_t m = bm + ty * 8 + i;
        #pragma unroll
        for (int j = 0; j < 8; j += 4) {
            const int n = bn + tx * 8 + j;
            float4 v;
            v.x = acc[i][j + 0] + bias[n + 0];
            v.y = acc[i][j + 1] + bias[n + 1];
            v.z = acc[i][j + 2] + bias[n + 2];
            v.w = acc[i][j + 3] + bias[n + 3];
            if (RELU) {
                v.x = fmaxf(v.x, 0.f); v.y = fmaxf(v.y, 0.f);
                v.z = fmaxf(v.z, 0.f); v.w = fmaxf(v.w, 0.f);
            }
            *(float4*)&C[m * N + n] = v;
        }
    }
}

// ---------------------------------------------------------------------------
// Recurrence: h_t = tanh(h_{t-1} * w_diag[h,n] + R_t[b,h,n]), lane-parallel.
// One thread per (b, h, n) lane; 2048 sequential steps, no inter-thread deps.
// ---------------------------------------------------------------------------
__global__ void recur_kernel(const float* __restrict__ R,
                             const float* __restrict__ W_h,
                             float* __restrict__ Hout)
{
    const int gid = blockIdx.x * blockDim.x + threadIdx.x;  // 0..4095
    if (gid >= BATCH * DMODEL) return;
    const int b  = gid >> 9;        // /512
    const int hn = gid & 511;       // h*64 + n

    // w_diag[h,n] = sum_k W_h[h,n,k]
    float w = 0.f;
    const float* wrow = W_h + (size_t)hn * DK;   // (h*64+n)*64
    #pragma unroll
    for (int k = 0; k < DK; k++) w += wrow[k];

    float hstate = 0.f;
    const size_t stride = (size_t)BATCH * DMODEL;   // 4096
    size_t idx = (size_t)b * DMODEL + hn;
    #pragma unroll 4
    for (int s = 0; s < SEQ; s++) {
        const float r = R[idx];
        hstate = tanhf(fmaf(hstate, w, r));
        Hout[idx] = hstate;
        idx += stride;
    }
}

// ---------------------------------------------------------------------------
// Flash-style attention, fp32, exact online softmax.
// grid = (SEQ/64, BATCH*HEADS); block = 256 (16x16, 4x4 micro-tile).
// scores = (Q . K) * 1/8 + (k>q ? 1.0 : 0.0)   <-- torch bool-mask quirk
// ---------------------------------------------------------------------------
__global__ void __launch_bounds__(256)
attn_kernel(const float* __restrict__ Q, const float* __restrict__ Hk,
            const float* __restrict__ V, float* __restrict__ O)
{
    __shared__ float Qs[DK][64];   // [d][q]   (transposed)
    __shared__ float Ks[DK][64];   // [d][k]   (transposed)
    __shared__ float Vs[64][DK];   // [k][d]
    __shared__ float Ps[64][68];   // [q][k]   (padded, 16B-aligned rows)

    const int tid = threadIdx.x;
    const int ty  = tid >> 4;      // 0..15
    const int tx  = tid & 15;      // 0..15
    const int bh  = blockIdx.y;
    const int b   = bh >> 3;
    const int h   = bh & 7;
    const int q0  = blockIdx.x << 6;

    // --- load Q tile (transposed) ---
    {
        const int r  = tid >> 2;              // 0..63
        const int d0 = (tid & 3) << 4;        // 0,16,32,48
        const float* src = Q + ((size_t)(q0 + r) * BATCH + b) * DMODEL + h * DK + d0;
        #pragma unroll
        for (int j = 0; j < 16; j += 4) {
            float4 v4 = *(const float4*)(src + j);
            Qs[d0 + j + 0][r] = v4.x;
            Qs[d0 + j + 1][r] = v4.y;
            Qs[d0 + j + 2][r] = v4.z;
            Qs[d0 + j + 3][r] = v4.w;
        }
    }

    float o[4][4] = {};
    float mrow[4], lrow[4];
    #pragma unroll
    for (int i = 0; i < 4; i++) { mrow[i] = -1e30f; lrow[i] = 0.f; }
    const float scale = 0.125f;   // 1/sqrt(64)

    for (int k0 = 0; k0 < SEQ; k0 += 64) {
        // --- load K (transposed) and V tiles ---
        {
            const int r  = tid >> 2;
            const int d0 = (tid & 3) << 4;
            const size_t gb = ((size_t)(k0 + r) * BATCH + b) * DMODEL + h * DK + d0;
            const float* ksrc = Hk + gb;
            const float* vsrc = V  + gb;
            #pragma unroll
            for (int j = 0; j < 16; j += 4) {
                float4 v4 = *(const float4*)(ksrc + j);
                Ks[d0 + j + 0][r] = v4.x;
                Ks[d0 + j + 1][r] = v4.y;
                Ks[d0 + j + 2][r] = v4.z;
                Ks[d0 + j + 3][r] = v4.w;
                *(float4*)&Vs[r][d0 + j] = *(const float4*)(vsrc + j);
            }
        }
        __syncthreads();

        // --- S tile: s[i][j] = sum_d Q[q][d] * K[k][d] ---
        float s[4][4] = {};
        #pragma unroll
        for (int d = 0; d < DK; d++) {
            float4 qv = *(const float4*)&Qs[d][ty << 2];
            float4 kv = *(const float4*)&Ks[d][tx << 2];
            float qa[4] = {qv.x, qv.y, qv.z, qv.w};
            float ka[4] = {kv.x, kv.y, kv.z, kv.w};
            #pragma unroll
            for (int i = 0; i < 4; i++)
                #pragma unroll
                for (int j = 0; j < 4; j++)
                    s[i][j] = fmaf(qa[i], ka[j], s[i][j]);
        }

        // --- scale + mask + online softmax update ---
        #pragma unroll
        for (int i = 0; i < 4; i++) {
            const int qg = q0 + (ty << 2) + i;
            float tmax = -1e30f;
            #pragma unroll
            for (int j = 0; j < 4; j++) {
                const int kg = k0 + (tx << 2) + j;
                s[i][j] = s[i][j] * scale + ((kg > qg) ? 1.0f : 0.0f);
                tmax = fmaxf(tmax, s[i][j]);
            }
            #pragma unroll
            for (int mm = 8; mm > 0; mm >>= 1)
                tmax = fmaxf(tmax, __shfl_xor_sync(0xffffffffu, tmax, mm));
            const float mnew = fmaxf(mrow[i], tmax);
            const float corr = __expf(mrow[i] - mnew);
            float tsum = 0.f;
            #pragma unroll
            for (int j = 0; j < 4; j++) {
                s[i][j] = __expf(s[i][j] - mnew);
                tsum += s[i][j];
            }
            #pragma unroll
            for (int mm = 8; mm > 0; mm >>= 1)
                tsum += __shfl_xor_sync(0xffffffffu, tsum, mm);
            lrow[i] = lrow[i] * corr + tsum;
            mrow[i] = mnew;
            #pragma unroll
            for (int j = 0; j < 4; j++) o[i][j] *= corr;
        }

        // --- write P tile ---
        #pragma unroll
        for (int i = 0; i < 4; i++)
            *(float4*)&Ps[(ty << 2) + i][tx << 2] =
                make_float4(s[i][0], s[i][1], s[i][2], s[i][3]);
        __syncthreads();

        // --- O += P @ V ---
        #pragma unroll
        for (int k = 0; k < 64; k++) {
            float4 vv = *(const float4*)&Vs[k][tx << 2];
            float va[4] = {vv.x, vv.y, vv.z, vv.w};
            #pragma unroll
            for (int i = 0; i < 4; i++) {
                const float p = Ps[(ty << 2) + i][k];
                #pragma unroll
                for (int j = 0; j < 4; j++)
                    o[i][j] = fmaf(p, va[j], o[i][j]);
            }
        }
        __syncthreads();
    }

    // --- epilogue: normalize & store ---
    #pragma unroll
    for (int i = 0; i < 4; i++) {
        const float inv = 1.f / lrow[i];
        float* dst = O + ((size_t)(q0 + (ty << 2) + i) * BATCH + b) * DMODEL
                       + h * DK + (tx << 2);
        *(float4*)dst = make_float4(o[i][0]*inv, o[i][1]*inv, o[i][2]*inv, o[i][3]*inv);
    }
}

// ---------------------------------------------------------------------------
// Fused residual-add + LayerNorm. One warp per 512-wide row; two-pass (exact).
// ---------------------------------------------------------------------------
__global__ void __launch_bounds__(256)
add_ln_kernel(const float* __restrict__ X, const float* __restrict__ Y,
              const float* __restrict__ gamma, const float* __restrict__ beta,
              float* __restrict__ out)
{
    const int warp = (blockIdx.x * blockDim.x + threadIdx.x) >> 5;
    const int lane = threadIdx.x & 31;
    if (warp >= TTOK) return;

    const float* xr = X + (size_t)warp * DMODEL;
    const float* yr = Y + (size_t)warp * DMODEL;

    float v[16];
    float sum = 0.f;
    #pragma unroll
    for (int i = 0; i < 16; i++) {
        v[i] = xr[lane + i * 32] + yr[lane + i * 32];
        sum += v[i];
    }
    #pragma unroll
    for (int m = 16; m > 0; m >>= 1) sum += __shfl_xor_sync(0xffffffffu, sum, m);
    const float mu = sum * (1.f / DMODEL);

    float var = 0.f;
    #pragma unroll
    for (int i = 0; i < 16; i++) { const float d = v[i] - mu; var = fmaf(d, d, var); }
    #pragma unroll
    for (int m = 16; m > 0; m >>= 1) var += __shfl_xor_sync(0xffffffffu, var, m);
    const float rstd = rsqrtf(var * (1.f / DMODEL) + 1e-5f);

    float* orow = out + (size_t)warp * DMODEL;
    #pragma unroll
    for (int i = 0; i < 16; i++) {
        const int c = lane + i * 32;
        orow[c] = (v[i] - mu) * rstd * gamma[c] + beta[c];
    }
}

// ---------------------------------------------------------------------------
// Launch orchestration
// ---------------------------------------------------------------------------
extern "C" void kernel_launch(void* const* d_in, const int* in_sizes, int n_in,
                              void* d_out, int out_size)
{
    const float* x     = (const float*)d_in[0];
    const float* Wq    = (const float*)d_in[1];
    const float* bq    = (const float*)d_in[2];
    const float* Wv    = (const float*)d_in[3];
    const float* bv    = (const float*)d_in[4];
    const float* Wr    = (const float*)d_in[5];
    const float* br    = (const float*)d_in[6];
    const float* W_h   = (const float*)d_in[7];
    const float* Wo    = (const float*)d_in[8];
    const float* bo    = (const float*)d_in[9];
    const float* ln1_g = (const float*)d_in[10];
    const float* ln1_b = (const float*)d_in[11];
    const float* Wf1   = (const float*)d_in[12];
    const float* bf1   = (const float*)d_in[13];
    const float* Wf2   = (const float*)d_in[14];
    const float* bf2   = (const float*)d_in[15];
    const float* ln2_g = (const float*)d_in[16];
    const float* ln2_b = (const float*)d_in[17];
    float* out = (float*)d_out;

    // Symbol addresses: memoized on the (pre-capture) correctness call, so the
    // captured call issues launches only.
    static float *pQ = nullptr, *pV, *pR, *pH, *pAttn, *pTmp, *pX1, *pFF;
    if (!pQ) {
        cudaGetSymbolAddress((void**)&pQ,    g_Q);
        cudaGetSymbolAddress((void**)&pV,    g_V);
        cudaGetSymbolAddress((void**)&pR,    g_R);
        cudaGetSymbolAddress((void**)&pH,    g_H);
        cudaGetSymbolAddress((void**)&pAttn, g_attn);
        cudaGetSymbolAddress((void**)&pTmp,  g_tmp);
        cudaGetSymbolAddress((void**)&pX1,   g_x1);
        cudaGetSymbolAddress((void**)&pFF,   g_ff);
    }

    const dim3 gP (DMODEL / 128, TTOK / 128);   // (4, 128) N=512 GEMMs
    const dim3 gF1(DFF    / 128, TTOK / 128);   // (16, 128) ff1
    const dim3 gAt(SEQ / 64, BATCH * HEADS);    // (32, 64)
    const dim3 gLN(TTOK / 8, 1);                // 8 warps/block

    // 1) Q, V, R projections  (C = x @ W^T + b)
    gemm_bias<true,  false><<<gP, 256>>>(x, Wq, bq, pQ, TTOK, DMODEL, DMODEL);
    gemm_bias<true,  false><<<gP, 256>>>(x, Wv, bv, pV, TTOK, DMODEL, DMODEL);
    gemm_bias<true,  false><<<gP, 256>>>(x, Wr, br, pR, TTOK, DMODEL, DMODEL);

    // 2) recurrence -> keys H
    recur_kernel<<<16, 256>>>(pR, W_h, pH);

    // 3) attention (flash, exact)
    attn_kernel<<<gAt, 256>>>(pQ, pH, pV, pAttn);

    // 4) output projection
    gemm_bias<true,  false><<<gP, 256>>>(pAttn, Wo, bo, pTmp, TTOK, DMODEL, DMODEL);

    // 5) x1 = LN1(x + attn_proj)
    add_ln_kernel<<<gLN, 256>>>(x, pTmp, ln1_g, ln1_b, pX1);

    // 6) ff hidden = relu(x1 @ Wf1 + bf1)
    gemm_bias<false, true ><<<gF1, 256>>>(pX1, Wf1, bf1, pFF, TTOK, DFF, DMODEL);

    // 7) ff out = ff @ Wf2 + bf2
    gemm_bias<false, false><<<gP, 256>>>(pFF, Wf2, bf2, pTmp, TTOK, DMODEL, DFF);

    // 8) out = LN2(x1 + ff_out)   (token order t = s*B+b == output layout)
    add_ln_kernel<<<gLN, 256>>>(pX1, pTmp, ln2_g, ln2_b, out);
}

// round 2
// speedup vs baseline: 2.7933x; 2.7933x over previous
#include <cuda_runtime.h>
#include <cuda_bf16.h>
#include <cstdint>

// ---------------------------------------------------------------------------
// Problem constants
// ---------------------------------------------------------------------------
#define SEQ    2048
#define BATCH  8
#define DMODEL 512
#define HEADS  8
#define DK     64
#define DFF    2048
#define TTOK   (SEQ * BATCH)          // 16384 tokens, t = s*BATCH + b

// ---------------------------------------------------------------------------
// Device scratch (static; cudaMalloc forbidden)
// ---------------------------------------------------------------------------
__device__ float g_Q   [TTOK * DMODEL];
__device__ float g_V   [TTOK * DMODEL];
__device__ float g_R   [TTOK * DMODEL];
__device__ float g_H   [TTOK * DMODEL];
__device__ float g_attn[TTOK * DMODEL];
__device__ float g_tmp [TTOK * DMODEL];
__device__ float g_x1  [TTOK * DMODEL];
__device__ float g_ff  [TTOK * DFF];
__device__ float g_Wf1T[DFF * DMODEL];   // [2048][512]
__device__ float g_Wf2T[DMODEL * DFF];   // [512][2048]

// ---------------------------------------------------------------------------
// tf32 helpers
// ---------------------------------------------------------------------------
__device__ __forceinline__ float to_tf32(float x) {
    uint32_t u;
    asm("cvt.rna.tf32.f32 %0, %1;" : "=r"(u) : "f"(x));
    return __uint_as_float(u);
}
__device__ __forceinline__ void mma_tf32(float c[4],
                                         uint32_t a0, uint32_t a1, uint32_t a2, uint32_t a3,
                                         uint32_t b0, uint32_t b1) {
    asm volatile(
        "mma.sync.aligned.m16n8k8.row.col.f32.tf32.tf32.f32 "
        "{%0,%1,%2,%3}, {%4,%5,%6,%7}, {%8,%9}, {%0,%1,%2,%3};\n"
        : "+f"(c[0]), "+f"(c[1]), "+f"(c[2]), "+f"(c[3])
        : "r"(a0), "r"(a1), "r"(a2), "r"(a3), "r"(b0), "r"(b1));
}
__device__ __forceinline__ uint32_t fu(float x) { return __float_as_uint(x); }

// ---------------------------------------------------------------------------
// tf32 tensor-core GEMM:  C[M,N] = A[M,K] @ W^T + bias,  W is [N][K] row-major.
// Block 128x128, BK=32, 256 threads (8 warps, 4x2), warp tile 32x64.
// ---------------------------------------------------------------------------
template<bool RELU>
__global__ void __launch_bounds__(256)
gemm_mma(const float* __restrict__ A, const float* __restrict__ W,
         const float* __restrict__ bias, float* __restrict__ C,
         int M, int N, int K)
{
    __shared__ float As[128][36];   // [m][k], pad 36 (36%32==4 -> conflict-free frags)
    __shared__ float Bs[128][36];   // [n][k]

    const int tid  = threadIdx.x;
    const int bm   = blockIdx.y * 128;
    const int bn   = blockIdx.x * 128;
    const int warp = tid >> 5, lane = tid & 31;
    const int g = lane >> 2, t = lane & 3;
    const int wm = (warp >> 1) * 32;   // warp m offset (0,32,64,96)
    const int wn = (warp &  1) * 64;   // warp n offset (0,64)

    float acc[2][8][4] = {};

    for (int k0 = 0; k0 < K; k0 += 32) {
        #pragma unroll
        for (int i = 0; i < 4; i++) {
            const int idx = tid + i * 256;     // 0..1023
            const int r   = idx >> 3;          // 0..127
            const int kq  = (idx & 7) * 4;     // 0..28
            float4 a4 = *(const float4*)&A[(size_t)(bm + r) * K + k0 + kq];
            a4.x = to_tf32(a4.x); a4.y = to_tf32(a4.y);
            a4.z = to_tf32(a4.z); a4.w = to_tf32(a4.w);
            *(float4*)&As[r][kq] = a4;
            float4 b4 = *(const float4*)&W[(size_t)(bn + r) * K + k0 + kq];
            b4.x = to_tf32(b4.x); b4.y = to_tf32(b4.y);
            b4.z = to_tf32(b4.z); b4.w = to_tf32(b4.w);
            *(float4*)&Bs[r][kq] = b4;
        }
        __syncthreads();

        #pragma unroll
        for (int kk = 0; kk < 32; kk += 8) {
            uint32_t af[2][4], bf[8][2];
            #pragma unroll
            for (int mt = 0; mt < 2; mt++) {
                const int r = wm + mt * 16 + g;
                af[mt][0] = fu(As[r    ][kk + t    ]);
                af[mt][1] = fu(As[r + 8][kk + t    ]);
                af[mt][2] = fu(As[r    ][kk + t + 4]);
                af[mt][3] = fu(As[r + 8][kk + t + 4]);
            }
            #pragma unroll
            for (int nt = 0; nt < 8; nt++) {
                const int c = wn + nt * 8 + g;
                bf[nt][0] = fu(Bs[c][kk + t    ]);
                bf[nt][1] = fu(Bs[c][kk + t + 4]);
            }
            #pragma unroll
            for (int mt = 0; mt < 2; mt++)
                #pragma unroll
                for (int nt = 0; nt < 8; nt++)
                    mma_tf32(acc[mt][nt], af[mt][0], af[mt][1], af[mt][2], af[mt][3],
                             bf[nt][0], bf[nt][1]);
        }
        __syncthreads();
    }

    #pragma unroll
    for (int mt = 0; mt < 2; mt++) {
        const int r0 = bm + wm + mt * 16 + g;
        #pragma unroll
        for (int nt = 0; nt < 8; nt++) {
            const int c = bn + wn + nt * 8 + 2 * t;
            float2 v0, v1;
            v0.x = acc[mt][nt][0] + bias[c];
            v0.y = acc[mt][nt][1] + bias[c + 1];
            v1.x = acc[mt][nt][2] + bias[c];
            v1.y = acc[mt][nt][3] + bias[c + 1];
            if (RELU) {
                v0.x = fmaxf(v0.x, 0.f); v0.y = fmaxf(v0.y, 0.f);
                v1.x = fmaxf(v1.x, 0.f); v1.y = fmaxf(v1.y, 0.f);
            }
            *(float2*)&C[(size_t)r0 * N + c]       = v0;
            *(float2*)&C[(size_t)(r0 + 8) * N + c] = v1;
        }
    }
}

// ---------------------------------------------------------------------------
// Transpose: out[c][r] = in[r][c], in is [R][Cc]
// ---------------------------------------------------------------------------
__global__ void __launch_bounds__(256)
transpose_kernel(const float* __restrict__ in, float* __restrict__ out, int R, int Cc)
{
    __shared__ float tile[32][33];
    const int c0 = blockIdx.x * 32, r0 = blockIdx.y * 32;
    const int tx = threadIdx.x & 31, ty = threadIdx.x >> 5;   // 32x8
    #pragma unroll
    for (int i = 0; i < 4; i++)
        tile[ty + i * 8][tx] = in[(size_t)(r0 + ty + i * 8) * Cc + c0 + tx];
    __syncthreads();
    #pragma unroll
    for (int i = 0; i < 4; i++)
        out[(size_t)(c0 + ty + i * 8) * R + r0 + tx] = tile[tx][ty + i * 8];
}

// ---------------------------------------------------------------------------
// Recurrence: h_t = tanh(h_{t-1} * w_diag + r_t), lane-parallel, approx tanh.
// ---------------------------------------------------------------------------
__global__ void recur_kernel(const float* __restrict__ R,
                             const float* __restrict__ W_h,
                             float* __restrict__ Hout)
{
    const int gid = blockIdx.x * blockDim.x + threadIdx.x;  // 0..4095
    if (gid >= BATCH * DMODEL) return;
    const int b  = gid >> 9;
    const int hn = gid & 511;

    float w = 0.f;
    const float* wrow = W_h + (size_t)hn * DK;
    #pragma unroll
    for (int k = 0; k < DK; k++) w += wrow[k];

    float hstate = 0.f;
    const size_t stride = (size_t)BATCH * DMODEL;
    size_t idx = (size_t)b * DMODEL + hn;
    #pragma unroll 8
    for (int s = 0; s < SEQ; s++) {
        const float r = R[idx];
        float x = fmaf(hstate, w, r);
        asm("tanh.approx.f32 %0, %1;" : "=f"(hstate) : "f"(x));
        Hout[idx] = hstate;
        idx += stride;
    }
}

// ---------------------------------------------------------------------------
// Flash attention, tf32 mma, exact online softmax in fp32 fragments.
// Block = 256 thr (8 warps), q-tile 128 (16 rows/warp), key-tile 64.
// scores = (Q.K)*0.125 + (k>q ? 1.0 : 0.0)
// ---------------------------------------------------------------------------
#define ATTN_SMEM ((64*72*2 + 128*68) * 4)   // Ks + Vs + Ps = 71680 B

__global__ void __launch_bounds__(256)
attn_mma(const float* __restrict__ Q, const float* __restrict__ Hk,
         const float* __restrict__ V, float* __restrict__ O)
{
    extern __shared__ float sm[];
    float (*Ks)[72] = (float(*)[72])sm;               // [key][d] pad 72 (%32==8)
    float (*Vs)[72] = (float(*)[72])(sm + 64 * 72);   // [key][d]
    float (*Ps)[68] = (float(*)[68])(sm + 2 * 64 * 72); // [q][*] pad 68 (%32==4)

    const int tid  = threadIdx.x;
    const int warp = tid >> 5, lane = tid & 31;
    const int g = lane >> 2, t = lane & 3;
    const int bh = blockIdx.y;
    const int b  = bh >> 3, h = bh & 7;
    const int q0 = blockIdx.x << 7;          // 128 q rows per block

    // ---- stage Q tile into Ps, then preload Q fragments to registers ----
    #pragma unroll
    for (int i = 0; i < 8; i++) {
        const int idx = tid + i * 256;       // 0..2047 float4s
        const int r   = idx >> 4;            // 0..127
        const int dq  = (idx & 15) * 4;      // 0..60
        float4 v4 = *(const float4*)&Q[((size_t)(q0 + r) * BATCH + b) * DMODEL + h * DK + dq];
        v4.x = to_tf32(v4.x); v4.y = to_tf32(v4.y);
        v4.z = to_tf32(v4.z); v4.w = to_tf32(v4.w);
        *(float4*)&Ps[r][dq] = v4;
    }
    __syncthreads();

    uint32_t qf[8][4];
    {
        const int r = warp * 16 + g;
        #pragma unroll
        for (int kk = 0; kk < 8; kk++) {
            const int d = kk * 8 + t;
            qf[kk][0] = fu(Ps[r    ][d    ]);
            qf[kk][1] = fu(Ps[r + 8][d    ]);
            qf[kk][2] = fu(Ps[r    ][d + 4]);
            qf[kk][3] = fu(Ps[r + 8][d + 4]);
        }
    }
    __syncthreads();

    float o[8][4] = {};
    float mrow[2] = {-1e30f, -1e30f};
    float lrow[2] = {0.f, 0.f};
    const float scale = 0.125f;

    for (int k0 = 0; k0 < SEQ; k0 += 64) {
        // ---- load K, V tiles ----
        #pragma unroll
        for (int i = 0; i < 4; i++) {
            const int idx = tid + i * 256;   // 0..1023 float4s
            const int r   = idx >> 4;        // 0..63
            const int dq  = (idx & 15) * 4;
            const size_t ga = ((size_t)(k0 + r) * BATCH + b) * DMODEL + h * DK + dq;
            float4 kv = *(const float4*)&Hk[ga];
            kv.x = to_tf32(kv.x); kv.y = to_tf32(kv.y);
            kv.z = to_tf32(kv.z); kv.w = to_tf32(kv.w);
            *(float4*)&Ks[r][dq] = kv;
            float4 vv = *(const float4*)&V[ga];
            vv.x = to_tf32(vv.x); vv.y = to_tf32(vv.y);
            vv.z = to_tf32(vv.z); vv.w = to_tf32(vv.w);
            *(float4*)&Vs[r][dq] = vv;
        }
        __syncthreads();

        // ---- S = Q @ K^T  (m16 x n64, k=64) ----
        float s[8][4] = {};
        #pragma unroll
        for (int kk = 0; kk < 8; kk++) {
            uint32_t bf[8][2];
            #pragma unroll
            for (int nt = 0; nt < 8; nt++) {
                const int key = nt * 8 + g;
                bf[nt][0] = fu(Ks[key][kk * 8 + t    ]);
                bf[nt][1] = fu(Ks[key][kk * 8 + t + 4]);
            }
            #pragma unroll
            for (int nt = 0; nt < 8; nt++)
                mma_tf32(s[nt], qf[kk][0], qf[kk][1], qf[kk][2], qf[kk][3],
                         bf[nt][0], bf[nt][1]);
        }

        // ---- scale + mask ----
        const int qg0 = q0 + warp * 16 + g;
        #pragma unroll
        for (int nt = 0; nt < 8; nt++) {
            const int kg = k0 + nt * 8 + 2 * t;
            s[nt][0] = s[nt][0] * scale + ((kg     > qg0    ) ? 1.f : 0.f);
            s[nt][1] = s[nt][1] * scale + ((kg + 1 > qg0    ) ? 1.f : 0.f);
            s[nt][2] = s[nt][2] * scale + ((kg     > qg0 + 8) ? 1.f : 0.f);
            s[nt][3] = s[nt][3] * scale + ((kg + 1 > qg0 + 8) ? 1.f : 0.f);
        }

        // ---- online softmax (2 rows per thread: g and g+8) ----
        #pragma unroll
        for (int ri = 0; ri < 2; ri++) {
            float tm = -1e30f;
            #pragma unroll
            for (int nt = 0; nt < 8; nt++) {
                tm = fmaxf(tm, s[nt][2 * ri]);
                tm = fmaxf(tm, s[nt][2 * ri + 1]);
            }
            tm = fmaxf(tm, __shfl_xor_sync(0xffffffffu, tm, 1));
            tm = fmaxf(tm, __shfl_xor_sync(0xffffffffu, tm, 2));
            const float mnew = fmaxf(mrow[ri], tm);
            const float corr = __expf(mrow[ri] - mnew);
            float ts = 0.f;
            #pragma unroll
            for (int nt = 0; nt < 8; nt++) {
                s[nt][2 * ri]     = __expf(s[nt][2 * ri]     - mnew);
                s[nt][2 * ri + 1] = __expf(s[nt][2 * ri + 1] - mnew);
                ts += s[nt][2 * ri] + s[nt][2 * ri + 1];
            }
            ts += __shfl_xor_sync(0xffffffffu, ts, 1);
            ts += __shfl_xor_sync(0xffffffffu, ts, 2);
            lrow[ri] = lrow[ri] * corr + ts;
            mrow[ri] = mnew;
            #pragma unroll
            for (int nt = 0; nt < 8; nt++) {
                o[nt][2 * ri]     *= corr;
                o[nt][2 * ri + 1] *= corr;
            }
        }

        // ---- write P tile (this warp's 16 rows only) ----
        {
            const int r = warp * 16 + g;
            #pragma unroll
            for (int nt = 0; nt < 8; nt++) {
                const int c = nt * 8 + 2 * t;
                Ps[r    ][c]     = to_tf32(s[nt][0]);
                Ps[r    ][c + 1] = to_tf32(s[nt][1]);
                Ps[r + 8][c]     = to_tf32(s[nt][2]);
                Ps[r + 8][c + 1] = to_tf32(s[nt][3]);
            }
        }
        __syncwarp();

        // ---- O += P @ V  (k = 64 keys) ----
        #pragma unroll
        for (int kk = 0; kk < 8; kk++) {
            const int r = warp * 16 + g;
            const int kb = kk * 8;
            uint32_t a0 = fu(Ps[r    ][kb + t    ]);
            uint32_t a1 = fu(Ps[r + 8][kb + t    ]);
            uint32_t a2 = fu(Ps[r    ][kb + t + 4]);
            uint32_t a3 = fu(Ps[r + 8][kb + t + 4]);
            #pragma unroll
            for (int nt = 0; nt < 8; nt++) {
                uint32_t b0 = fu(Vs[kb + t    ][nt * 8 + g]);
                uint32_t b1 = fu(Vs[kb + t + 4][nt * 8 + g]);
                mma_tf32(o[nt], a0, a1, a2, a3, b0, b1);
            }
        }
        __syncthreads();   // protect Ks/Vs for next tile
    }

    // ---- epilogue: normalize & store ----
    const float inv0 = 1.f / lrow[0];
    const float inv1 = 1.f / lrow[1];
    const int r0 = q0 + warp * 16 + g;
    #pragma unroll
    for (int nt = 0; nt < 8; nt++) {
        const int c = h * DK + nt * 8 + 2 * t;
        float2 v0 = make_float2(o[nt][0] * inv0, o[nt][1] * inv0);
        float2 v1 = make_float2(o[nt][2] * inv1, o[nt][3] * inv1);
        *(float2*)&O[((size_t)r0 * BATCH + b) * DMODEL + c]       = v0;
        *(float2*)&O[((size_t)(r0 + 8) * BATCH + b) * DMODEL + c] = v1;
    }
}

// ---------------------------------------------------------------------------
// Fused residual-add + LayerNorm (one warp per row, exact two-pass)
// ---------------------------------------------------------------------------
__global__ void __launch_bounds__(256)
add_ln_kernel(const float* __restrict__ X, const float* __restrict__ Y,
              const float* __restrict__ gamma, const float* __restrict__ beta,
              float* __restrict__ out)
{
    const int warp = (blockIdx.x * blockDim.x + threadIdx.x) >> 5;
    const int lane = threadIdx.x & 31;
    if (warp >= TTOK) return;

    const float* xr = X + (size_t)warp * DMODEL;
    const float* yr = Y + (size_t)warp * DMODEL;

    float v[16];
    float sum = 0.f;
    #pragma unroll
    for (int i = 0; i < 16; i++) {
        v[i] = xr[lane + i * 32] + yr[lane + i * 32];
        sum += v[i];
    }
    #pragma unroll
    for (int m = 16; m > 0; m >>= 1) sum += __shfl_xor_sync(0xffffffffu, sum, m);
    const float mu = sum * (1.f / DMODEL);

    float var = 0.f;
    #pragma unroll
    for (int i = 0; i < 16; i++) { const float d = v[i] - mu; var = fmaf(d, d, var); }
    #pragma unroll
    for (int m = 16; m > 0; m >>= 1) var += __shfl_xor_sync(0xffffffffu, var, m);
    const float rstd = rsqrtf(var * (1.f / DMODEL) + 1e-5f);

    float* orow = out + (size_t)warp * DMODEL;
    #pragma unroll
    for (int i = 0; i < 16; i++) {
        const int c = lane + i * 32;
        orow[c] = (v[i] - mu) * rstd * gamma[c] + beta[c];
    }
}

// ---------------------------------------------------------------------------
// Launch orchestration
// ---------------------------------------------------------------------------
extern "C" void kernel_launch(void* const* d_in, const int* in_sizes, int n_in,
                              void* d_out, int out_size)
{
    const float* x     = (const float*)d_in[0];
    const float* Wq    = (const float*)d_in[1];
    const float* bq    = (const float*)d_in[2];
    const float* Wv    = (const float*)d_in[3];
    const float* bv    = (const float*)d_in[4];
    const float* Wr    = (const float*)d_in[5];
    const float* br    = (const float*)d_in[6];
    const float* W_h   = (const float*)d_in[7];
    const float* Wo    = (const float*)d_in[8];
    const float* bo    = (const float*)d_in[9];
    const float* ln1_g = (const float*)d_in[10];
    const float* ln1_b = (const float*)d_in[11];
    const float* Wf1   = (const float*)d_in[12];
    const float* bf1   = (const float*)d_in[13];
    const float* Wf2   = (const float*)d_in[14];
    const float* bf2   = (const float*)d_in[15];
    const float* ln2_g = (const float*)d_in[16];
    const float* ln2_b = (const float*)d_in[17];
    float* out = (float*)d_out;

    static float *pQ = nullptr, *pV, *pR, *pH, *pAttn, *pTmp, *pX1, *pFF, *pW1T, *pW2T;
    if (!pQ) {
        cudaGetSymbolAddress((void**)&pQ,    g_Q);
        cudaGetSymbolAddress((void**)&pV,    g_V);
        cudaGetSymbolAddress((void**)&pR,    g_R);
        cudaGetSymbolAddress((void**)&pH,    g_H);
        cudaGetSymbolAddress((void**)&pAttn, g_attn);
        cudaGetSymbolAddress((void**)&pTmp,  g_tmp);
        cudaGetSymbolAddress((void**)&pX1,   g_x1);
        cudaGetSymbolAddress((void**)&pFF,   g_ff);
        cudaGetSymbolAddress((void**)&pW1T,  g_Wf1T);
        cudaGetSymbolAddress((void**)&pW2T,  g_Wf2T);
        cudaFuncSetAttribute(attn_mma, cudaFuncAttributeMaxDynamicSharedMemorySize,
                             ATTN_SMEM);
    }

    const dim3 gP (DMODEL / 128, TTOK / 128);   // (4, 128)
    const dim3 gF1(DFF    / 128, TTOK / 128);   // (16, 128)
    const dim3 gAt(SEQ / 128, BATCH * HEADS);   // (16, 64)
    const dim3 gLN(TTOK / 8, 1);

    // 0) transpose FF weights to [N][K]
    transpose_kernel<<<dim3(DFF / 32, DMODEL / 32), 256>>>(Wf1, pW1T, DMODEL, DFF);
    transpose_kernel<<<dim3(DMODEL / 32, DFF / 32), 256>>>(Wf2, pW2T, DFF, DMODEL);

    // 1) Q, V, R projections
    gemm_mma<false><<<gP, 256>>>(x, Wq, bq, pQ, TTOK, DMODEL, DMODEL);
    gemm_mma<false><<<gP, 256>>>(x, Wv, bv, pV, TTOK, DMODEL, DMODEL);
    gemm_mma<false><<<gP, 256>>>(x, Wr, br, pR, TTOK, DMODEL, DMODEL);

    // 2) recurrence -> keys H
    recur_kernel<<<16, 256>>>(pR, W_h, pH);

    // 3) attention
    attn_mma<<<gAt, 256, ATTN_SMEM>>>(pQ, pH, pV, pAttn);

    // 4) output projection
    gemm_mma<false><<<gP, 256>>>(pAttn, Wo, bo, pTmp, TTOK, DMODEL, DMODEL);

    // 5) x1 = LN1(x + attn_proj)
    add_ln_kernel<<<gLN, 256>>>(x, pTmp, ln1_g, ln1_b, pX1);

    // 6) ff = relu(x1 @ Wf1 + bf1)
    gemm_mma<true ><<<gF1, 256>>>(pX1, pW1T, bf1, pFF, TTOK, DFF, DMODEL);

    // 7) ff2 = ff @ Wf2 + bf2
    gemm_mma<false><<<gP, 256>>>(pFF, pW2T, bf2, pTmp, TTOK, DMODEL, DFF);

    // 8) out = LN2(x1 + ff2)
    add_ln_kernel<<<gLN, 256>>>(pX1, pTmp, ln2_g, ln2_b, out);
}

// round 4
// speedup vs baseline: 3.2595x; 1.1669x over previous
#include <cuda_runtime.h>
#include <cuda_bf16.h>
#include <cstdint>

// ---------------------------------------------------------------------------
// Problem constants
// ---------------------------------------------------------------------------
#define SEQ    2048
#define BATCH  8
#define DMODEL 512
#define HEADS  8
#define DK     64
#define DFF    2048
#define TTOK   (SEQ * BATCH)          // 16384 tokens, t = s*BATCH + b

// ---------------------------------------------------------------------------
// Device scratch (static; cudaMalloc forbidden)
// ---------------------------------------------------------------------------
__device__ float g_Q   [TTOK * DMODEL];
__device__ float g_V   [TTOK * DMODEL];
__device__ float g_R   [TTOK * DMODEL];
__device__ float g_H   [TTOK * DMODEL];
__device__ float g_attn[TTOK * DMODEL];
__device__ float g_tmp [TTOK * DMODEL];
__device__ float g_x1  [TTOK * DMODEL];
__device__ float g_ff  [TTOK * DFF];
__device__ float g_Wf1T[DFF * DMODEL];   // [2048][512]
__device__ float g_Wf2T[DMODEL * DFF];   // [512][2048]

// ---------------------------------------------------------------------------
// Helpers
// ---------------------------------------------------------------------------
__device__ __forceinline__ uint32_t smem_u32(const void* p) {
    uint32_t a;
    asm("{ .reg .u64 t; cvta.to.shared.u64 t, %1; cvt.u32.u64 %0, t; }"
        : "=r"(a) : "l"(p));
    return a;
}
__device__ __forceinline__ void cp16(uint32_t dst, const void* src) {
    asm volatile("cp.async.cg.shared.global [%0], [%1], 16;"
                 :: "r"(dst), "l"(src));
}
__device__ __forceinline__ void cp_commit() {
    asm volatile("cp.async.commit_group;" ::: "memory");
}
__device__ __forceinline__ void cp_wait1() {
    asm volatile("cp.async.wait_group 1;" ::: "memory");
}
__device__ __forceinline__ void cp_wait0() {
    asm volatile("cp.async.wait_group 0;" ::: "memory");
}
__device__ __forceinline__ float to_tf32(float x) {
    uint32_t u;
    asm("cvt.rna.tf32.f32 %0, %1;" : "=r"(u) : "f"(x));
    return __uint_as_float(u);
}
__device__ __forceinline__ void mma_tf32(float c[4],
                                         uint32_t a0, uint32_t a1, uint32_t a2, uint32_t a3,
                                         uint32_t b0, uint32_t b1) {
    asm volatile(
        "mma.sync.aligned.m16n8k8.row.col.f32.tf32.tf32.f32 "
        "{%0,%1,%2,%3}, {%4,%5,%6,%7}, {%8,%9}, {%0,%1,%2,%3};\n"
        : "+f"(c[0]), "+f"(c[1]), "+f"(c[2]), "+f"(c[3])
        : "r"(a0), "r"(a1), "r"(a2), "r"(a3), "r"(b0), "r"(b1));
}
__device__ __forceinline__ uint32_t fu(float x) { return __float_as_uint(x); }

// ---------------------------------------------------------------------------
// tf32 GEMM v2: C[M,N] = A[M,K] @ W^T + bias, W is [N][K] row-major.
// Block 128x128, 128 threads (4 warps, 2x2), warp tile 64x64.
// 3-stage cp.async pipeline, BK=32. Raw fp32 -> tf32 mma (HW truncation).
// ---------------------------------------------------------------------------
#define G_PITCH   36                         // floats; 36%32==4 -> conflict-free frags
#define G_AFL     (128 * G_PITCH)            // 4608 floats per A stage
#define G_STAGEF  (2 * G_AFL)                // 9216 floats (A + B)
#define GEMM_SMEM (3 * G_STAGEF * 4)         // 110592 B

template<bool RELU>
__global__ void __launch_bounds__(128)
gemm_mma2(const float* __restrict__ A, const float* __restrict__ W,
          const float* __restrict__ bias, float* __restrict__ C,
          int M, int N, int K)
{
    extern __shared__ float sm[];
    const int tid  = threadIdx.x;
    const int warp = tid >> 5, lane = tid & 31;
    const int g = lane >> 2, t = lane & 3;
    const int bm = blockIdx.y * 128;
    const int bn = blockIdx.x * 128;
    const int wm = (warp >> 1) * 64;
    const int wn = (warp &  1) * 64;

    const uint32_t sbase = smem_u32(sm);

    float acc[4][8][4] = {};

    const int KT = K >> 5;

    // stage filler: A(128x32) + B(128x32), 8 iters x 2 cp16 per thread
    auto fill = [&](int s, int kt) {
        const int k0 = kt << 5;
        const uint32_t st = sbase + (uint32_t)(s * G_STAGEF) * 4;
        #pragma unroll
        for (int i = 0; i < 8; i++) {
            const int idx = tid + i * 128;           // 0..1023
            const int r   = idx >> 3;                // 0..127
            const int kq  = (idx & 7) << 2;          // 0,4,...,28
            cp16(st + (uint32_t)(r * G_PITCH + kq) * 4,
                 A + (size_t)(bm + r) * K + k0 + kq);
            cp16(st + (uint32_t)(G_AFL + r * G_PITCH + kq) * 4,
                 W + (size_t)(bn + r) * K + k0 + kq);
        }
        cp_commit();
    };

    fill(0, 0);
    fill(1, 1);

    for (int kt = 0; kt < KT; kt++) {
        if (kt + 1 < KT) cp_wait1(); else cp_wait0();
        __syncthreads();

        if (kt + 2 < KT) fill((kt + 2) % 3, kt + 2);

        float (*As)[G_PITCH] = (float(*)[G_PITCH])(sm + (kt % 3) * G_STAGEF);
        float (*Bs)[G_PITCH] = (float(*)[G_PITCH])(sm + (kt % 3) * G_STAGEF + G_AFL);

        #pragma unroll
        for (int kk = 0; kk < 32; kk += 8) {
            uint32_t af[4][4], bf[8][2];
            #pragma unroll
            for (int mt = 0; mt < 4; mt++) {
                const int r = wm + mt * 16 + g;
                af[mt][0] = fu(As[r    ][kk + t    ]);
                af[mt][1] = fu(As[r + 8][kk + t    ]);
                af[mt][2] = fu(As[r    ][kk + t + 4]);
                af[mt][3] = fu(As[r + 8][kk + t + 4]);
            }
            #pragma unroll
            for (int nt = 0; nt < 8; nt++) {
                const int c = wn + nt * 8 + g;
                bf[nt][0] = fu(Bs[c][kk + t    ]);
                bf[nt][1] = fu(Bs[c][kk + t + 4]);
            }
            #pragma unroll
            for (int mt = 0; mt < 4; mt++)
                #pragma unroll
                for (int nt = 0; nt < 8; nt++)
                    mma_tf32(acc[mt][nt], af[mt][0], af[mt][1], af[mt][2], af[mt][3],
                             bf[nt][0], bf[nt][1]);
        }
        __syncthreads();
    }

    #pragma unroll
    for (int mt = 0; mt < 4; mt++) {
        const int r0 = bm + wm + mt * 16 + g;
        #pragma unroll
        for (int nt = 0; nt < 8; nt++) {
            const int c = bn + wn + nt * 8 + 2 * t;
            float2 v0, v1;
            v0.x = acc[mt][nt][0] + bias[c];
            v0.y = acc[mt][nt][1] + bias[c + 1];
            v1.x = acc[mt][nt][2] + bias[c];
            v1.y = acc[mt][nt][3] + bias[c + 1];
            if (RELU) {
                v0.x = fmaxf(v0.x, 0.f); v0.y = fmaxf(v0.y, 0.f);
                v1.x = fmaxf(v1.x, 0.f); v1.y = fmaxf(v1.y, 0.f);
            }
            *(float2*)&C[(size_t)r0 * N + c]       = v0;
            *(float2*)&C[(size_t)(r0 + 8) * N + c] = v1;
        }
    }
}

// ---------------------------------------------------------------------------
// Transpose: out[c][r] = in[r][c], in is [R][Cc]
// ---------------------------------------------------------------------------
__global__ void __launch_bounds__(256)
transpose_kernel(const float* __restrict__ in, float* __restrict__ out, int R, int Cc)
{
    __shared__ float tile[32][33];
    const int c0 = blockIdx.x * 32, r0 = blockIdx.y * 32;
    const int tx = threadIdx.x & 31, ty = threadIdx.x >> 5;   // 32x8
    #pragma unroll
    for (int i = 0; i < 4; i++)
        tile[ty + i * 8][tx] = in[(size_t)(r0 + ty + i * 8) * Cc + c0 + tx];
    __syncthreads();
    #pragma unroll
    for (int i = 0; i < 4; i++)
        out[(size_t)(c0 + ty + i * 8) * R + r0 + tx] = tile[tx][ty + i * 8];
}

// ---------------------------------------------------------------------------
// Recurrence: h_t = tanh(h_{t-1} * w_diag + r_t), lane-parallel, approx tanh.
// ---------------------------------------------------------------------------
__global__ void recur_kernel(const float* __restrict__ R,
                             const float* __restrict__ W_h,
                             float* __restrict__ Hout)
{
    const int gid = blockIdx.x * blockDim.x + threadIdx.x;  // 0..4095
    if (gid >= BATCH * DMODEL) return;
    const int b  = gid >> 9;
    const int hn = gid & 511;

    float w = 0.f;
    const float* wrow = W_h + (size_t)hn * DK;
    #pragma unroll
    for (int k = 0; k < DK; k++) w += wrow[k];

    float hstate = 0.f;
    const size_t stride = (size_t)BATCH * DMODEL;
    size_t idx = (size_t)b * DMODEL + hn;
    #pragma unroll 8
    for (int s = 0; s < SEQ; s++) {
        const float r = R[idx];
        float x = fmaf(hstate, w, r);
        asm("tanh.approx.f32 %0, %1;" : "=f"(hstate) : "f"(x));
        Hout[idx] = hstate;
        idx += stride;
    }
}

// ---------------------------------------------------------------------------
// Flash attention v2: 4 warps, q-tile 128 (32 q/warp), key-tile 64.
// Q in smem (reloaded per k-tile), halved K/V fragment duplication.
// Pitches: Q/K/P = 68 (row-type loads conflict-free), V = 72 (col-type).
// scores = (Q.K)*0.125 + (k>q ? 1.0 : 0.0)
// ---------------------------------------------------------------------------
#define QS_OFF  0
#define KS_OFF  (128 * 68)
#define VS_OFF  (KS_OFF + 64 * 68)
#define PS_OFF  (VS_OFF + 64 * 72)
#define ATTN_SMEM ((PS_OFF + 128 * 68) * 4)   // 105472 B

__global__ void __launch_bounds__(128)
attn_mma2(const float* __restrict__ Q, const float* __restrict__ Hk,
          const float* __restrict__ V, float* __restrict__ O)
{
    extern __shared__ float sm[];
    float (*Qs)[68] = (float(*)[68])(sm + QS_OFF);
    float (*Ks)[68] = (float(*)[68])(sm + KS_OFF);
    float (*Vs)[72] = (float(*)[72])(sm + VS_OFF);
    float (*Ps)[68] = (float(*)[68])(sm + PS_OFF);

    const int tid  = threadIdx.x;
    const int warp = tid >> 5, lane = tid & 31;
    const int g = lane >> 2, t = lane & 3;
    const int bh = blockIdx.y;
    const int b  = bh >> 3, h = bh & 7;
    const int q0 = blockIdx.x << 7;          // 128 q rows per block

    // ---- stage Q tile (tf32 rna) ----
    #pragma unroll
    for (int i = 0; i < 16; i++) {
        const int idx = tid + i * 128;       // 0..2047 float4s
        const int r   = idx >> 4;            // 0..127
        const int dq  = (idx & 15) * 4;      // 0..60
        float4 v4 = *(const float4*)&Q[((size_t)(q0 + r) * BATCH + b) * DMODEL + h * DK + dq];
        v4.x = to_tf32(v4.x); v4.y = to_tf32(v4.y);
        v4.z = to_tf32(v4.z); v4.w = to_tf32(v4.w);
        *(float4*)&Qs[r][dq] = v4;
    }

    float o[2][8][4] = {};
    float mrow[4] = {-1e30f, -1e30f, -1e30f, -1e30f};
    float lrow[4] = {0.f, 0.f, 0.f, 0.f};
    const float scale = 0.125f;

    __syncthreads();

    for (int k0 = 0; k0 < SEQ; k0 += 64) {
        // ---- stage K, V tiles ----
        #pragma unroll
        for (int i = 0; i < 8; i++) {
            const int idx = tid + i * 128;   // 0..1023 float4s
            const int r   = idx >> 4;        // 0..63
            const int dq  = (idx & 15) * 4;
            const size_t ga = ((size_t)(k0 + r) * BATCH + b) * DMODEL + h * DK + dq;
            float4 kv = *(const float4*)&Hk[ga];
            kv.x = to_tf32(kv.x); kv.y = to_tf32(kv.y);
            kv.z = to_tf32(kv.z); kv.w = to_tf32(kv.w);
            *(float4*)&Ks[r][dq] = kv;
            float4 vv = *(const float4*)&V[ga];
            vv.x = to_tf32(vv.x); vv.y = to_tf32(vv.y);
            vv.z = to_tf32(vv.z); vv.w = to_tf32(vv.w);
            *(float4*)&Vs[r][dq] = vv;
        }
        __syncthreads();

        #pragma unroll
        for (int mt = 0; mt < 2; mt++) {
            const int qrow = warp * 32 + mt * 16;

            // ---- S = Q @ K^T  (16q x 64k, d=64) ----
            float s[8][4] = {};
            #pragma unroll
            for (int kk = 0; kk < 8; kk++) {
                const int d = kk * 8;
                const uint32_t a0 = fu(Qs[qrow + g    ][d + t    ]);
                const uint32_t a1 = fu(Qs[qrow + 8 + g][d + t    ]);
                const uint32_t a2 = fu(Qs[qrow + g    ][d + t + 4]);
                const uint32_t a3 = fu(Qs[qrow + 8 + g][d + t + 4]);
                #pragma unroll
                for (int nt = 0; nt < 8; nt++) {
                    const uint32_t b0 = fu(Ks[nt * 8 + g][d + t    ]);
                    const uint32_t b1 = fu(Ks[nt * 8 + g][d + t + 4]);
                    mma_tf32(s[nt], a0, a1, a2, a3, b0, b1);
                }
            }

            // ---- scale + mask ----
            const int qg0 = q0 + qrow + g;
            #pragma unroll
            for (int nt = 0; nt < 8; nt++) {
                const int kg = k0 + nt * 8 + 2 * t;
                s[nt][0] = s[nt][0] * scale + ((kg     > qg0    ) ? 1.f : 0.f);
                s[nt][1] = s[nt][1] * scale + ((kg + 1 > qg0    ) ? 1.f : 0.f);
                s[nt][2] = s[nt][2] * scale + ((kg     > qg0 + 8) ? 1.f : 0.f);
                s[nt][3] = s[nt][3] * scale + ((kg + 1 > qg0 + 8) ? 1.f : 0.f);
            }

            // ---- online softmax (rows g and g+8 of this m-tile) ----
            #pragma unroll
            for (int half = 0; half < 2; half++) {
                const int ri = mt * 2 + half;
                float tm = -1e30f;
                #pragma unroll
                for (int nt = 0; nt < 8; nt++) {
                    tm = fmaxf(tm, s[nt][2 * half]);
                    tm = fmaxf(tm, s[nt][2 * half + 1]);
                }
                tm = fmaxf(tm, __shfl_xor_sync(0xffffffffu, tm, 1));
                tm = fmaxf(tm, __shfl_xor_sync(0xffffffffu, tm, 2));
                const float mnew = fmaxf(mrow[ri], tm);
                const float corr = __expf(mrow[ri] - mnew);
                float ts = 0.f;
                #pragma unroll
                for (int nt = 0; nt < 8; nt++) {
                    s[nt][2 * half]     = __expf(s[nt][2 * half]     - mnew);
                    s[nt][2 * half + 1] = __expf(s[nt][2 * half + 1] - mnew);
                    ts += s[nt][2 * half] + s[nt][2 * half + 1];
                }
                ts += __shfl_xor_sync(0xffffffffu, ts, 1);
                ts += __shfl_xor_sync(0xffffffffu, ts, 2);
                lrow[ri] = lrow[ri] * corr + ts;
                mrow[ri] = mnew;
                #pragma unroll
                for (int nt = 0; nt < 8; nt++) {
                    o[mt][nt][2 * half]     *= corr;
                    o[mt][nt][2 * half + 1] *= corr;
                }
            }

            // ---- write P (this warp's 16 rows) ----
            #pragma unroll
            for (int nt = 0; nt < 8; nt++) {
                const int c = nt * 8 + 2 * t;
                Ps[qrow + g    ][c]     = to_tf32(s[nt][0]);
                Ps[qrow + g    ][c + 1] = to_tf32(s[nt][1]);
                Ps[qrow + 8 + g][c]     = to_tf32(s[nt][2]);
                Ps[qrow + 8 + g][c + 1] = to_tf32(s[nt][3]);
            }
            __syncwarp();

            // ---- O += P @ V ----
            #pragma unroll
            for (int kk = 0; kk < 8; kk++) {
                const int kb = kk * 8;
                const uint32_t a0 = fu(Ps[qrow + g    ][kb + t    ]);
                const uint32_t a1 = fu(Ps[qrow + 8 + g][kb + t    ]);
                const uint32_t a2 = fu(Ps[qrow + g    ][kb + t + 4]);
                const uint32_t a3 = fu(Ps[qrow + 8 + g][kb + t + 4]);
                #pragma unroll
                for (int nt = 0; nt < 8; nt++) {
                    const uint32_t b0 = fu(Vs[kb + t    ][nt * 8 + g]);
                    const uint32_t b1 = fu(Vs[kb + t + 4][nt * 8 + g]);
                    mma_tf32(o[mt][nt], a0, a1, a2, a3, b0, b1);
                }
            }
        }
        __syncthreads();   // protect Ks/Vs for next tile
    }

    // ---- epilogue: normalize & store ----
    #pragma unroll
    for (int mt = 0; mt < 2; mt++) {
        const float inv0 = 1.f / lrow[mt * 2];
        const float inv1 = 1.f / lrow[mt * 2 + 1];
        const int r0 = q0 + warp * 32 + mt * 16 + g;
        #pragma unroll
        for (int nt = 0; nt < 8; nt++) {
            const int c = h * DK + nt * 8 + 2 * t;
            float2 v0 = make_float2(o[mt][nt][0] * inv0, o[mt][nt][1] * inv0);
            float2 v1 = make_float2(o[mt][nt][2] * inv1, o[mt][nt][3] * inv1);
            *(float2*)&O[((size_t)r0 * BATCH + b) * DMODEL + c]       = v0;
            *(float2*)&O[((size_t)(r0 + 8) * BATCH + b) * DMODEL + c] = v1;
        }
    }
}

// ---------------------------------------------------------------------------
// Fused residual-add + LayerNorm (one warp per row, exact two-pass)
// ---------------------------------------------------------------------------
__global__ void __launch_bounds__(256)
add_ln_kernel(const float* __restrict__ X, const float* __restrict__ Y,
              const float* __restrict__ gamma, const float* __restrict__ beta,
              float* __restrict__ out)
{
    const int warp = (blockIdx.x * blockDim.x + threadIdx.x) >> 5;
    const int lane = threadIdx.x & 31;
    if (warp >= TTOK) return;

    const float* xr = X + (size_t)warp * DMODEL;
    const float* yr = Y + (size_t)warp * DMODEL;

    float v[16];
    float sum = 0.f;
    #pragma unroll
    for (int i = 0; i < 16; i++) {
        v[i] = xr[lane + i * 32] + yr[lane + i * 32];
        sum += v[i];
    }
    #pragma unroll
    for (int m = 16; m > 0; m >>= 1) sum += __shfl_xor_sync(0xffffffffu, sum, m);
    const float mu = sum * (1.f / DMODEL);

    float var = 0.f;
    #pragma unroll
    for (int i = 0; i < 16; i++) { const float d = v[i] - mu; var = fmaf(d, d, var); }
    #pragma unroll
    for (int m = 16; m > 0; m >>= 1) var += __shfl_xor_sync(0xffffffffu, var, m);
    const float rstd = rsqrtf(var * (1.f / DMODEL) + 1e-5f);

    float* orow = out + (size_t)warp * DMODEL;
    #pragma unroll
    for (int i = 0; i < 16; i++) {
        const int c = lane + i * 32;
        orow[c] = (v[i] - mu) * rstd * gamma[c] + beta[c];
    }
}

// ---------------------------------------------------------------------------
// Launch orchestration
// ---------------------------------------------------------------------------
extern "C" void kernel_launch(void* const* d_in, const int* in_sizes, int n_in,
                              void* d_out, int out_size)
{
    const float* x     = (const float*)d_in[0];
    const float* Wq    = (const float*)d_in[1];
    const float* bq    = (const float*)d_in[2];
    const float* Wv    = (const float*)d_in[3];
    const float* bv    = (const float*)d_in[4];
    const float* Wr    = (const float*)d_in[5];
    const float* br    = (const float*)d_in[6];
    const float* W_h   = (const float*)d_in[7];
    const float* Wo    = (const float*)d_in[8];
    const float* bo    = (const float*)d_in[9];
    const float* ln1_g = (const float*)d_in[10];
    const float* ln1_b = (const float*)d_in[11];
    const float* Wf1   = (const float*)d_in[12];
    const float* bf1   = (const float*)d_in[13];
    const float* Wf2   = (const float*)d_in[14];
    const float* bf2   = (const float*)d_in[15];
    const float* ln2_g = (const float*)d_in[16];
    const float* ln2_b = (const float*)d_in[17];
    float* out = (float*)d_out;

    static float *pQ = nullptr, *pV, *pR, *pH, *pAttn, *pTmp, *pX1, *pFF, *pW1T, *pW2T;
    if (!pQ) {
        cudaGetSymbolAddress((void**)&pQ,    g_Q);
        cudaGetSymbolAddress((void**)&pV,    g_V);
        cudaGetSymbolAddress((void**)&pR,    g_R);
        cudaGetSymbolAddress((void**)&pH,    g_H);
        cudaGetSymbolAddress((void**)&pAttn, g_attn);
        cudaGetSymbolAddress((void**)&pTmp,  g_tmp);
        cudaGetSymbolAddress((void**)&pX1,   g_x1);
        cudaGetSymbolAddress((void**)&pFF,   g_ff);
        cudaGetSymbolAddress((void**)&pW1T,  g_Wf1T);
        cudaGetSymbolAddress((void**)&pW2T,  g_Wf2T);
        cudaFuncSetAttribute(attn_mma2, cudaFuncAttributeMaxDynamicSharedMemorySize,
                             ATTN_SMEM);
        cudaFuncSetAttribute(gemm_mma2<false>,
                             cudaFuncAttributeMaxDynamicSharedMemorySize, GEMM_SMEM);
        cudaFuncSetAttribute(gemm_mma2<true>,
                             cudaFuncAttributeMaxDynamicSharedMemorySize, GEMM_SMEM);
    }

    const dim3 gP (DMODEL / 128, TTOK / 128);   // (4, 128)
    const dim3 gF1(DFF    / 128, TTOK / 128);   // (16, 128)
    const dim3 gAt(SEQ / 128, BATCH * HEADS);   // (16, 64)
    const dim3 gLN(TTOK / 8, 1);

    // 0) transpose FF weights to [N][K]
    transpose_kernel<<<dim3(DFF / 32, DMODEL / 32), 256>>>(Wf1, pW1T, DMODEL, DFF);
    transpose_kernel<<<dim3(DMODEL / 32, DFF / 32), 256>>>(Wf2, pW2T, DFF, DMODEL);

    // 1) Q, V, R projections
    gemm_mma2<false><<<gP, 128, GEMM_SMEM>>>(x, Wq, bq, pQ, TTOK, DMODEL, DMODEL);
    gemm_mma2<false><<<gP, 128, GEMM_SMEM>>>(x, Wv, bv, pV, TTOK, DMODEL, DMODEL);
    gemm_mma2<false><<<gP, 128, GEMM_SMEM>>>(x, Wr, br, pR, TTOK, DMODEL, DMODEL);

    // 2) recurrence -> keys H
    recur_kernel<<<16, 256>>>(pR, W_h, pH);

    // 3) attention
    attn_mma2<<<gAt, 128, ATTN_SMEM>>>(pQ, pH, pV, pAttn);

    // 4) output projection
    gemm_mma2<false><<<gP, 128, GEMM_SMEM>>>(pAttn, Wo, bo, pTmp, TTOK, DMODEL, DMODEL);

    // 5) x1 = LN1(x + attn_proj)
    add_ln_kernel<<<gLN, 256>>>(x, pTmp, ln1_g, ln1_b, pX1);

    // 6) ff = relu(x1 @ Wf1 + bf1)
    gemm_mma2<true ><<<gF1, 128, GEMM_SMEM>>>(pX1, pW1T, bf1, pFF, TTOK, DFF, DMODEL);

    // 7) ff2 = ff @ Wf2 + bf2
    gemm_mma2<false><<<gP, 128, GEMM_SMEM>>>(pFF, pW2T, bf2, pTmp, TTOK, DMODEL, DFF);

    // 8) out = LN2(x1 + ff2)
    add_ln_kernel<<<gLN, 256>>>(pX1, pTmp, ln2_g, ln2_b, out);
}

// round 5
// speedup vs baseline: 4.7608x; 1.4606x over previous
#include <cuda_runtime.h>
#include <cuda_fp16.h>
#include <cstdint>

// ---------------------------------------------------------------------------
// Problem constants
// ---------------------------------------------------------------------------
#define SEQ    2048
#define BATCH  8
#define DMODEL 512
#define HEADS  8
#define DK     64
#define DFF    2048
#define TTOK   (SEQ * BATCH)          // 16384 tokens, t = s*BATCH + b

// ---------------------------------------------------------------------------
// Device scratch (static; cudaMalloc forbidden)
// ---------------------------------------------------------------------------
__device__ __half g_xh  [TTOK * DMODEL];
__device__ __half g_Qh  [TTOK * DMODEL];
__device__ __half g_Vh  [TTOK * DMODEL];
__device__ __half g_Rh  [TTOK * DMODEL];
__device__ __half g_Hh  [TTOK * DMODEL];
__device__ __half g_attnh[TTOK * DMODEL];
__device__ __half g_x1h [TTOK * DMODEL];
__device__ __half g_ffh [TTOK * DFF];
__device__ float  g_tmp [TTOK * DMODEL];
__device__ float  g_x1  [TTOK * DMODEL];
__device__ __half g_Wqh [DMODEL * DMODEL];
__device__ __half g_Wvh [DMODEL * DMODEL];
__device__ __half g_Wrh [DMODEL * DMODEL];
__device__ __half g_Woh [DMODEL * DMODEL];
__device__ __half g_Wf1T[DFF * DMODEL];   // [2048][512] half
__device__ __half g_Wf2T[DMODEL * DFF];   // [512][2048] half

// ---------------------------------------------------------------------------
// Helpers
// ---------------------------------------------------------------------------
__device__ __forceinline__ uint32_t smem_u32(const void* p) {
    uint32_t a;
    asm("{ .reg .u64 t; cvta.to.shared.u64 t, %1; cvt.u32.u64 %0, t; }"
        : "=r"(a) : "l"(p));
    return a;
}
__device__ __forceinline__ void cp16(uint32_t dst, const void* src) {
    asm volatile("cp.async.cg.shared.global [%0], [%1], 16;"
                 :: "r"(dst), "l"(src));
}
__device__ __forceinline__ void cp_commit() {
    asm volatile("cp.async.commit_group;" ::: "memory");
}
__device__ __forceinline__ void cp_wait1() {
    asm volatile("cp.async.wait_group 1;" ::: "memory");
}
__device__ __forceinline__ void cp_wait0() {
    asm volatile("cp.async.wait_group 0;" ::: "memory");
}
__device__ __forceinline__ void mma_f16(float c[4],
                                        uint32_t a0, uint32_t a1, uint32_t a2, uint32_t a3,
                                        uint32_t b0, uint32_t b1) {
    asm volatile(
        "mma.sync.aligned.m16n8k16.row.col.f32.f16.f16.f32 "
        "{%0,%1,%2,%3}, {%4,%5,%6,%7}, {%8,%9}, {%0,%1,%2,%3};\n"
        : "+f"(c[0]), "+f"(c[1]), "+f"(c[2]), "+f"(c[3])
        : "r"(a0), "r"(a1), "r"(a2), "r"(a3), "r"(b0), "r"(b1));
}
__device__ __forceinline__ uint32_t ldh2(const __half* p) {
    return *(const uint32_t*)p;
}

// ---------------------------------------------------------------------------
// fp16 GEMM: C[M,N] = A[M,K] @ W^T + bias, A/W half, W is [N][K] row-major.
// Block 128x128, 128 threads (4 warps, 2x2), warp tile 64x64.
// BK = 64 halfs, 3-stage cp.async pipeline. fp32 accumulate.
// ---------------------------------------------------------------------------
#define GP        72                         // pitch in halfs (36 words, %32==4)
#define G_AH      (128 * GP)                 // 9216 halfs per A tile
#define G_STAGEH  (2 * G_AH)                 // 18432 halfs (A + B)
#define GEMM_SMEM (3 * G_STAGEH * 2)         // 110592 B

template<bool RELU, bool OUTH>
__global__ void __launch_bounds__(128)
gemm_h(const __half* __restrict__ A, const __half* __restrict__ W,
       const float* __restrict__ bias, void* __restrict__ Cout,
       int M, int N, int K)
{
    extern __shared__ __half sh[];
    const int tid  = threadIdx.x;
    const int warp = tid >> 5, lane = tid & 31;
    const int g = lane >> 2, t = lane & 3;
    const int bm = blockIdx.y * 128;
    const int bn = blockIdx.x * 128;
    const int wm = (warp >> 1) * 64;
    const int wn = (warp &  1) * 64;

    const uint32_t sbase = smem_u32(sh);

    float acc[4][8][4] = {};
    const int KT = K >> 6;   // k-tiles of 64 halfs

    auto fill = [&](int s, int kt) {
        const int k0 = kt << 6;
        const uint32_t st = sbase + (uint32_t)(s * G_STAGEH) * 2;
        #pragma unroll
        for (int i = 0; i < 8; i++) {
            const int idx = tid + i * 128;           // 0..1023
            const int r   = idx >> 3;                // 0..127
            const int kq  = (idx & 7) << 3;          // 0,8,...,56
            cp16(st + (uint32_t)(r * GP + kq) * 2,
                 A + (size_t)(bm + r) * K + k0 + kq);
            cp16(st + (uint32_t)(G_AH + r * GP + kq) * 2,
                 W + (size_t)(bn + r) * K + k0 + kq);
        }
        cp_commit();
    };

    fill(0, 0);
    fill(1, 1);

    for (int kt = 0; kt < KT; kt++) {
        if (kt + 1 < KT) cp_wait1(); else cp_wait0();
        __syncthreads();

        if (kt + 2 < KT) fill((kt + 2) % 3, kt + 2);

        const __half (*As)[GP] = (const __half(*)[GP])(sh + (kt % 3) * G_STAGEH);
        const __half (*Bs)[GP] = (const __half(*)[GP])(sh + (kt % 3) * G_STAGEH + G_AH);

        #pragma unroll
        for (int kk = 0; kk < 64; kk += 16) {
            uint32_t af[4][4], bf[8][2];
            #pragma unroll
            for (int mt = 0; mt < 4; mt++) {
                const int r = wm + mt * 16 + g;
                af[mt][0] = ldh2(&As[r    ][kk + 2 * t    ]);
                af[mt][1] = ldh2(&As[r + 8][kk + 2 * t    ]);
                af[mt][2] = ldh2(&As[r    ][kk + 2 * t + 8]);
                af[mt][3] = ldh2(&As[r + 8][kk + 2 * t + 8]);
            }
            #pragma unroll
            for (int nt = 0; nt < 8; nt++) {
                const int c = wn + nt * 8 + g;
                bf[nt][0] = ldh2(&Bs[c][kk + 2 * t    ]);
                bf[nt][1] = ldh2(&Bs[c][kk + 2 * t + 8]);
            }
            #pragma unroll
            for (int mt = 0; mt < 4; mt++)
                #pragma unroll
                for (int nt = 0; nt < 8; nt++)
                    mma_f16(acc[mt][nt], af[mt][0], af[mt][1], af[mt][2], af[mt][3],
                            bf[nt][0], bf[nt][1]);
        }
        __syncthreads();
    }

    #pragma unroll
    for (int mt = 0; mt < 4; mt++) {
        const int r0 = bm + wm + mt * 16 + g;
        #pragma unroll
        for (int nt = 0; nt < 8; nt++) {
            const int c = bn + wn + nt * 8 + 2 * t;
            float v0 = acc[mt][nt][0] + bias[c];
            float v1 = acc[mt][nt][1] + bias[c + 1];
            float v2 = acc[mt][nt][2] + bias[c];
            float v3 = acc[mt][nt][3] + bias[c + 1];
            if (RELU) {
                v0 = fmaxf(v0, 0.f); v1 = fmaxf(v1, 0.f);
                v2 = fmaxf(v2, 0.f); v3 = fmaxf(v3, 0.f);
            }
            if (OUTH) {
                __half* C = (__half*)Cout;
                *(__half2*)&C[(size_t)r0 * N + c]       = __floats2half2_rn(v0, v1);
                *(__half2*)&C[(size_t)(r0 + 8) * N + c] = __floats2half2_rn(v2, v3);
            } else {
                float* C = (float*)Cout;
                *(float2*)&C[(size_t)r0 * N + c]       = make_float2(v0, v1);
                *(float2*)&C[(size_t)(r0 + 8) * N + c] = make_float2(v2, v3);
            }
        }
    }
}

// ---------------------------------------------------------------------------
// fp32 -> fp16 conversion (vectorized)
// ---------------------------------------------------------------------------
__global__ void __launch_bounds__(256)
f2h_kernel(const float* __restrict__ in, __half* __restrict__ out, int n)
{
    const int i = (blockIdx.x * blockDim.x + threadIdx.x) * 4;
    if (i < n) {
        float4 v = *(const float4*)(in + i);
        *(__half2*)(out + i)     = __floats2half2_rn(v.x, v.y);
        *(__half2*)(out + i + 2) = __floats2half2_rn(v.z, v.w);
    }
}

// ---------------------------------------------------------------------------
// Transpose + convert: out[c][r] = half(in[r][c]), in fp32 [R][Cc]
// ---------------------------------------------------------------------------
__global__ void __launch_bounds__(256)
transpose_h_kernel(const float* __restrict__ in, __half* __restrict__ out,
                   int R, int Cc)
{
    __shared__ float tile[32][33];
    const int c0 = blockIdx.x * 32, r0 = blockIdx.y * 32;
    const int tx = threadIdx.x & 31, ty = threadIdx.x >> 5;   // 32x8
    #pragma unroll
    for (int i = 0; i < 4; i++)
        tile[ty + i * 8][tx] = in[(size_t)(r0 + ty + i * 8) * Cc + c0 + tx];
    __syncthreads();
    #pragma unroll
    for (int i = 0; i < 4; i++)
        out[(size_t)(c0 + ty + i * 8) * R + r0 + tx] =
            __float2half_rn(tile[tx][ty + i * 8]);
}

// ---------------------------------------------------------------------------
// Recurrence: h_t = tanh(h_{t-1} * w_diag + r_t), lane-parallel, half I/O.
// ---------------------------------------------------------------------------
__global__ void recur_kernel(const __half* __restrict__ R,
                             const float* __restrict__ W_h,
                             __half* __restrict__ Hout)
{
    const int gid = blockIdx.x * blockDim.x + threadIdx.x;  // 0..4095
    if (gid >= BATCH * DMODEL) return;
    const int b  = gid >> 9;
    const int hn = gid & 511;

    float w = 0.f;
    const float* wrow = W_h + (size_t)hn * DK;
    #pragma unroll
    for (int k = 0; k < DK; k++) w += wrow[k];

    float hstate = 0.f;
    const size_t stride = (size_t)BATCH * DMODEL;
    size_t idx = (size_t)b * DMODEL + hn;
    #pragma unroll 8
    for (int s = 0; s < SEQ; s++) {
        const float r = __half2float(R[idx]);
        float x = fmaf(hstate, w, r);
        asm("tanh.approx.f32 %0, %1;" : "=f"(hstate) : "f"(x));
        Hout[idx] = __float2half_rn(hstate);
        idx += stride;
    }
}

// ---------------------------------------------------------------------------
// Flash attention, fp16 mma, fp32 online softmax.
// 4 warps, q-tile 128 (32 q/warp), key-tile 64.
// Qs/Ks/Ps: [row][d/key] pitch 72; Vt: [d][key] pitch 72 (transposed at stage).
// scores = (Q.K)*0.125 + (k>q ? 1.0 : 0.0)
// ---------------------------------------------------------------------------
#define AP       72
#define QS_OFF   0
#define KS_OFF   (128 * AP)
#define VT_OFF   (KS_OFF + 64 * AP)
#define PS_OFF   (VT_OFF + 64 * AP)
#define ATTN_SMEM ((PS_OFF + 128 * AP) * 2)   // 55296 B

__global__ void __launch_bounds__(128)
attn_h(const __half* __restrict__ Q, const __half* __restrict__ Hk,
       const __half* __restrict__ V, __half* __restrict__ O)
{
    extern __shared__ __half sh[];
    __half (*Qs)[AP] = (__half(*)[AP])(sh + QS_OFF);
    __half (*Ks)[AP] = (__half(*)[AP])(sh + KS_OFF);
    __half (*Vt)[AP] = (__half(*)[AP])(sh + VT_OFF);
    __half (*Ps)[AP] = (__half(*)[AP])(sh + PS_OFF);

    const int tid  = threadIdx.x;
    const int warp = tid >> 5, lane = tid & 31;
    const int g = lane >> 2, t = lane & 3;
    const int bh = blockIdx.y;
    const int b  = bh >> 3, h = bh & 7;
    const int q0 = blockIdx.x << 7;          // 128 q rows per block

    // ---- stage Q tile (128 rows x 64 halfs) ----
    #pragma unroll
    for (int i = 0; i < 8; i++) {
        const int idx = tid + i * 128;       // 0..1023 8-half chunks
        const int r   = idx >> 3;            // 0..127
        const int dq  = (idx & 7) * 8;       // 0..56
        const size_t ga = ((size_t)(q0 + r) * BATCH + b) * DMODEL + h * DK + dq;
        *(float4*)&Qs[r][dq] = *(const float4*)&Q[ga];
    }

    float o[2][8][4] = {};
    float mrow[4] = {-1e30f, -1e30f, -1e30f, -1e30f};
    float lrow[4] = {0.f, 0.f, 0.f, 0.f};
    const float scale = 0.125f;

    __syncthreads();

    for (int k0 = 0; k0 < SEQ; k0 += 64) {
        // ---- stage K tile + V tile (transposed) ----
        #pragma unroll
        for (int i = 0; i < 4; i++) {
            const int idx = tid + i * 128;   // 0..511
            const int r   = idx >> 3;        // 0..63 (key)
            const int dq  = (idx & 7) * 8;   // 0..56
            const size_t ga = ((size_t)(k0 + r) * BATCH + b) * DMODEL + h * DK + dq;
            *(float4*)&Ks[r][dq] = *(const float4*)&Hk[ga];
            const __half* vp = &V[ga];
            #pragma unroll
            for (int j = 0; j < 8; j++)
                Vt[dq + j][r] = vp[j];
        }
        __syncthreads();

        #pragma unroll
        for (int mt = 0; mt < 2; mt++) {
            const int qrow = warp * 32 + mt * 16;

            // ---- S = Q @ K^T  (16q x 64k, d=64 in 4 k16 steps) ----
            float s[8][4] = {};
            #pragma unroll
            for (int kk = 0; kk < 64; kk += 16) {
                const uint32_t a0 = ldh2(&Qs[qrow + g    ][kk + 2 * t    ]);
                const uint32_t a1 = ldh2(&Qs[qrow + 8 + g][kk + 2 * t    ]);
                const uint32_t a2 = ldh2(&Qs[qrow + g    ][kk + 2 * t + 8]);
                const uint32_t a3 = ldh2(&Qs[qrow + 8 + g][kk + 2 * t + 8]);
                #pragma unroll
                for (int nt = 0; nt < 8; nt++) {
                    const uint32_t b0 = ldh2(&Ks[nt * 8 + g][kk + 2 * t    ]);
                    const uint32_t b1 = ldh2(&Ks[nt * 8 + g][kk + 2 * t + 8]);
                    mma_f16(s[nt], a0, a1, a2, a3, b0, b1);
                }
            }

            // ---- scale + mask ----
            const int qg0 = q0 + qrow + g;
            #pragma unroll
            for (int nt = 0; nt < 8; nt++) {
                const int kg = k0 + nt * 8 + 2 * t;
                s[nt][0] = s[nt][0] * scale + ((kg     > qg0    ) ? 1.f : 0.f);
                s[nt][1] = s[nt][1] * scale + ((kg + 1 > qg0    ) ? 1.f : 0.f);
                s[nt][2] = s[nt][2] * scale + ((kg     > qg0 + 8) ? 1.f : 0.f);
                s[nt][3] = s[nt][3] * scale + ((kg + 1 > qg0 + 8) ? 1.f : 0.f);
            }

            // ---- online softmax (rows g, g+8) ----
            #pragma unroll
            for (int half_i = 0; half_i < 2; half_i++) {
                const int ri = mt * 2 + half_i;
                float tm = -1e30f;
                #pragma unroll
                for (int nt = 0; nt < 8; nt++) {
                    tm = fmaxf(tm, s[nt][2 * half_i]);
                    tm = fmaxf(tm, s[nt][2 * half_i + 1]);
                }
                tm = fmaxf(tm, __shfl_xor_sync(0xffffffffu, tm, 1));
                tm = fmaxf(tm, __shfl_xor_sync(0xffffffffu, tm, 2));
                const float mnew = fmaxf(mrow[ri], tm);
                const float corr = __expf(mrow[ri] - mnew);
                float ts = 0.f;
                #pragma unroll
                for (int nt = 0; nt < 8; nt++) {
                    s[nt][2 * half_i]     = __expf(s[nt][2 * half_i]     - mnew);
                    s[nt][2 * half_i + 1] = __expf(s[nt][2 * half_i + 1] - mnew);
                    ts += s[nt][2 * half_i] + s[nt][2 * half_i + 1];
                }
                ts += __shfl_xor_sync(0xffffffffu, ts, 1);
                ts += __shfl_xor_sync(0xffffffffu, ts, 2);
                lrow[ri] = lrow[ri] * corr + ts;
                mrow[ri] = mnew;
                #pragma unroll
                for (int nt = 0; nt < 8; nt++) {
                    o[mt][nt][2 * half_i]     *= corr;
                    o[mt][nt][2 * half_i + 1] *= corr;
                }
            }

            // ---- write P (half) ----
            #pragma unroll
            for (int nt = 0; nt < 8; nt++) {
                const int c = nt * 8 + 2 * t;
                *(__half2*)&Ps[qrow + g    ][c] = __floats2half2_rn(s[nt][0], s[nt][1]);
                *(__half2*)&Ps[qrow + 8 + g][c] = __floats2half2_rn(s[nt][2], s[nt][3]);
            }
            __syncwarp();

            // ---- O += P @ V  (64 keys in 4 k16 steps) ----
            #pragma unroll
            for (int kb = 0; kb < 64; kb += 16) {
                const uint32_t a0 = ldh2(&Ps[qrow + g    ][kb + 2 * t    ]);
                const uint32_t a1 = ldh2(&Ps[qrow + 8 + g][kb + 2 * t    ]);
                const uint32_t a2 = ldh2(&Ps[qrow + g    ][kb + 2 * t + 8]);
                const uint32_t a3 = ldh2(&Ps[qrow + 8 + g][kb + 2 * t + 8]);
                #pragma unroll
                for (int nt = 0; nt < 8; nt++) {
                    const uint32_t b0 = ldh2(&Vt[nt * 8 + g][kb + 2 * t    ]);
                    const uint32_t b1 = ldh2(&Vt[nt * 8 + g][kb + 2 * t + 8]);
                    mma_f16(o[mt][nt], a0, a1, a2, a3, b0, b1);
                }
            }
        }
        __syncthreads();   // protect Ks/Vt for next tile
    }

    // ---- epilogue: normalize & store half ----
    #pragma unroll
    for (int mt = 0; mt < 2; mt++) {
        const float inv0 = 1.f / lrow[mt * 2];
        const float inv1 = 1.f / lrow[mt * 2 + 1];
        const int r0 = q0 + warp * 32 + mt * 16 + g;
        #pragma unroll
        for (int nt = 0; nt < 8; nt++) {
            const int c = h * DK + nt * 8 + 2 * t;
            *(__half2*)&O[((size_t)r0 * BATCH + b) * DMODEL + c] =
                __floats2half2_rn(o[mt][nt][0] * inv0, o[mt][nt][1] * inv0);
            *(__half2*)&O[((size_t)(r0 + 8) * BATCH + b) * DMODEL + c] =
                __floats2half2_rn(o[mt][nt][2] * inv1, o[mt][nt][3] * inv1);
        }
    }
}

// ---------------------------------------------------------------------------
// Fused residual-add + LayerNorm; optional half copy of the output.
// ---------------------------------------------------------------------------
__global__ void __launch_bounds__(256)
add_ln_kernel(const float* __restrict__ X, const float* __restrict__ Y,
              const float* __restrict__ gamma, const float* __restrict__ beta,
              float* __restrict__ out, __half* __restrict__ outh)
{
    const int warp = (blockIdx.x * blockDim.x + threadIdx.x) >> 5;
    const int lane = threadIdx.x & 31;
    if (warp >= TTOK) return;

    const float* xr = X + (size_t)warp * DMODEL;
    const float* yr = Y + (size_t)warp * DMODEL;

    float v[16];
    float sum = 0.f;
    #pragma unroll
    for (int i = 0; i < 16; i++) {
        v[i] = xr[lane + i * 32] + yr[lane + i * 32];
        sum += v[i];
    }
    #pragma unroll
    for (int m = 16; m > 0; m >>= 1) sum += __shfl_xor_sync(0xffffffffu, sum, m);
    const float mu = sum * (1.f / DMODEL);

    float var = 0.f;
    #pragma unroll
    for (int i = 0; i < 16; i++) { const float d = v[i] - mu; var = fmaf(d, d, var); }
    #pragma unroll
    for (int m = 16; m > 0; m >>= 1) var += __shfl_xor_sync(0xffffffffu, var, m);
    const float rstd = rsqrtf(var * (1.f / DMODEL) + 1e-5f);

    float* orow = out + (size_t)warp * DMODEL;
    #pragma unroll
    for (int i = 0; i < 16; i++) {
        const int c = lane + i * 32;
        const float val = (v[i] - mu) * rstd * gamma[c] + beta[c];
        orow[c] = val;
        if (outh) outh[(size_t)warp * DMODEL + c] = __float2half_rn(val);
    }
}

// ---------------------------------------------------------------------------
// Launch orchestration
// ---------------------------------------------------------------------------
extern "C" void kernel_launch(void* const* d_in, const int* in_sizes, int n_in,
                              void* d_out, int out_size)
{
    const float* x     = (const float*)d_in[0];
    const float* Wq    = (const float*)d_in[1];
    const float* bq    = (const float*)d_in[2];
    const float* Wv    = (const float*)d_in[3];
    const float* bv    = (const float*)d_in[4];
    const float* Wr    = (const float*)d_in[5];
    const float* br    = (const float*)d_in[6];
    const float* W_h   = (const float*)d_in[7];
    const float* Wo    = (const float*)d_in[8];
    const float* bo    = (const float*)d_in[9];
    const float* ln1_g = (const float*)d_in[10];
    const float* ln1_b = (const float*)d_in[11];
    const float* Wf1   = (const float*)d_in[12];
    const float* bf1   = (const float*)d_in[13];
    const float* Wf2   = (const float*)d_in[14];
    const float* bf2   = (const float*)d_in[15];
    const float* ln2_g = (const float*)d_in[16];
    const float* ln2_b = (const float*)d_in[17];
    float* out = (float*)d_out;

    static __half *pxh = nullptr, *pQh, *pVh, *pRh, *pHh, *pAh, *px1h, *pFFh,
                  *pWqh, *pWvh, *pWrh, *pWoh, *pW1T, *pW2T;
    static float *pTmp, *pX1;
    if (!pxh) {
        cudaGetSymbolAddress((void**)&pxh,  g_xh);
        cudaGetSymbolAddress((void**)&pQh,  g_Qh);
        cudaGetSymbolAddress((void**)&pVh,  g_Vh);
        cudaGetSymbolAddress((void**)&pRh,  g_Rh);
        cudaGetSymbolAddress((void**)&pHh,  g_Hh);
        cudaGetSymbolAddress((void**)&pAh,  g_attnh);
        cudaGetSymbolAddress((void**)&px1h, g_x1h);
        cudaGetSymbolAddress((void**)&pFFh, g_ffh);
        cudaGetSymbolAddress((void**)&pWqh, g_Wqh);
        cudaGetSymbolAddress((void**)&pWvh, g_Wvh);
        cudaGetSymbolAddress((void**)&pWrh, g_Wrh);
        cudaGetSymbolAddress((void**)&pWoh, g_Woh);
        cudaGetSymbolAddress((void**)&pW1T, g_Wf1T);
        cudaGetSymbolAddress((void**)&pW2T, g_Wf2T);
        cudaGetSymbolAddress((void**)&pTmp, g_tmp);
        cudaGetSymbolAddress((void**)&pX1,  g_x1);
        cudaFuncSetAttribute(attn_h, cudaFuncAttributeMaxDynamicSharedMemorySize,
                             ATTN_SMEM);
        cudaFuncSetAttribute(gemm_h<false, true>,
                             cudaFuncAttributeMaxDynamicSharedMemorySize, GEMM_SMEM);
        cudaFuncSetAttribute(gemm_h<false, false>,
                             cudaFuncAttributeMaxDynamicSharedMemorySize, GEMM_SMEM);
        cudaFuncSetAttribute(gemm_h<true, true>,
                             cudaFuncAttributeMaxDynamicSharedMemorySize, GEMM_SMEM);
    }

    const dim3 gP (DMODEL / 128, TTOK / 128);   // (4, 128)
    const dim3 gF1(DFF    / 128, TTOK / 128);   // (16, 128)
    const dim3 gAt(SEQ / 128, BATCH * HEADS);   // (16, 64)
    const dim3 gLN(TTOK / 8, 1);

    // 0) conversions
    f2h_kernel<<<(TTOK * DMODEL / 4 + 255) / 256, 256>>>(x, pxh, TTOK * DMODEL);
    f2h_kernel<<<(DMODEL * DMODEL / 4 + 255) / 256, 256>>>(Wq, pWqh, DMODEL * DMODEL);
    f2h_kernel<<<(DMODEL * DMODEL / 4 + 255) / 256, 256>>>(Wv, pWvh, DMODEL * DMODEL);
    f2h_kernel<<<(DMODEL * DMODEL / 4 + 255) / 256, 256>>>(Wr, pWrh, DMODEL * DMODEL);
    f2h_kernel<<<(DMODEL * DMODEL / 4 + 255) / 256, 256>>>(Wo, pWoh, DMODEL * DMODEL);
    transpose_h_kernel<<<dim3(DFF / 32, DMODEL / 32), 256>>>(Wf1, pW1T, DMODEL, DFF);
    transpose_h_kernel<<<dim3(DMODEL / 32, DFF / 32), 256>>>(Wf2, pW2T, DFF, DMODEL);

    // 1) Q, V, R projections (half out)
    gemm_h<false, true><<<gP, 128, GEMM_SMEM>>>(pxh, pWqh, bq, pQh, TTOK, DMODEL, DMODEL);
    gemm_h<false, true><<<gP, 128, GEMM_SMEM>>>(pxh, pWvh, bv, pVh, TTOK, DMODEL, DMODEL);
    gemm_h<false, true><<<gP, 128, GEMM_SMEM>>>(pxh, pWrh, br, pRh, TTOK, DMODEL, DMODEL);

    // 2) recurrence -> keys H
    recur_kernel<<<16, 256>>>(pRh, W_h, pHh);

    // 3) attention (half in/out)
    attn_h<<<gAt, 128, ATTN_SMEM>>>(pQh, pHh, pVh, pAh);

    // 4) output projection (fp32 out, feeds LN)
    gemm_h<false, false><<<gP, 128, GEMM_SMEM>>>(pAh, pWoh, bo, pTmp, TTOK, DMODEL, DMODEL);

    // 5) x1 = LN1(x + attn_proj): fp32 + half copies
    add_ln_kernel<<<gLN, 256>>>(x, pTmp, ln1_g, ln1_b, pX1, px1h);

    // 6) ff = relu(x1 @ Wf1 + bf1) (half out)
    gemm_h<true, true><<<gF1, 128, GEMM_SMEM>>>(px1h, pW1T, bf1, pFFh, TTOK, DFF, DMODEL);

    // 7) ff2 = ff @ Wf2 + bf2 (fp32 out, feeds LN)
    gemm_h<false, false><<<gP, 128, GEMM_SMEM>>>(pFFh, pW2T, bf2, pTmp, TTOK, DMODEL, DFF);

    // 8) out = LN2(x1 + ff2)
    add_ln_kernel<<<gLN, 256>>>(pX1, pTmp, ln2_g, ln2_b, out, nullptr);
}

// round 7
// speedup vs baseline: 4.9304x; 1.0356x over previous
#include <cuda_runtime.h>
#include <cuda_fp16.h>
#include <cstdint>

// ---------------------------------------------------------------------------
// Problem constants
// ---------------------------------------------------------------------------
#define SEQ    2048
#define BATCH  8
#define DMODEL 512
#define HEADS  8
#define DK     64
#define DFF    2048
#define TTOK   (SEQ * BATCH)          // 16384 tokens, t = s*BATCH + b

// ---------------------------------------------------------------------------
// Device scratch (static; cudaMalloc forbidden)
// ---------------------------------------------------------------------------
__device__ __half g_xh  [TTOK * DMODEL];
__device__ __half g_Qh  [TTOK * DMODEL];
__device__ __half g_Vh  [TTOK * DMODEL];
__device__ __half g_Rh  [TTOK * DMODEL];
__device__ __half g_Hh  [TTOK * DMODEL];
__device__ __half g_attnh[TTOK * DMODEL];
__device__ __half g_x1h [TTOK * DMODEL];
__device__ __half g_ffh [TTOK * DFF];
__device__ float  g_tmp [TTOK * DMODEL];
__device__ float  g_x1  [TTOK * DMODEL];
__device__ __half g_Wqh [DMODEL * DMODEL];
__device__ __half g_Wvh [DMODEL * DMODEL];
__device__ __half g_Wrh [DMODEL * DMODEL];
__device__ __half g_Woh [DMODEL * DMODEL];
__device__ __half g_Wf1T[DFF * DMODEL];   // [2048][512] half
__device__ __half g_Wf2T[DMODEL * DFF];   // [512][2048] half

// ---------------------------------------------------------------------------
// Helpers
// ---------------------------------------------------------------------------
__device__ __forceinline__ uint32_t smem_u32(const void* p) {
    uint32_t a;
    asm("{ .reg .u64 t; cvta.to.shared.u64 t, %1; cvt.u32.u64 %0, t; }"
        : "=r"(a) : "l"(p));
    return a;
}
__device__ __forceinline__ void cp16(uint32_t dst, const void* src) {
    asm volatile("cp.async.cg.shared.global [%0], [%1], 16;"
                 :: "r"(dst), "l"(src));
}
__device__ __forceinline__ void cp_commit() {
    asm volatile("cp.async.commit_group;" ::: "memory");
}
__device__ __forceinline__ void cp_wait1() {
    asm volatile("cp.async.wait_group 1;" ::: "memory");
}
__device__ __forceinline__ void cp_wait0() {
    asm volatile("cp.async.wait_group 0;" ::: "memory");
}
__device__ __forceinline__ void mma_f16(float c[4],
                                        uint32_t a0, uint32_t a1, uint32_t a2, uint32_t a3,
                                        uint32_t b0, uint32_t b1) {
    asm volatile(
        "mma.sync.aligned.m16n8k16.row.col.f32.f16.f16.f32 "
        "{%0,%1,%2,%3}, {%4,%5,%6,%7}, {%8,%9}, {%0,%1,%2,%3};\n"
        : "+f"(c[0]), "+f"(c[1]), "+f"(c[2]), "+f"(c[3])
        : "r"(a0), "r"(a1), "r"(a2), "r"(a3), "r"(b0), "r"(b1));
}
__device__ __forceinline__ void ldsm_x4(uint32_t& r0, uint32_t& r1,
                                        uint32_t& r2, uint32_t& r3, uint32_t addr) {
    asm volatile("ldmatrix.sync.aligned.m8n8.x4.shared.b16 {%0,%1,%2,%3}, [%4];"
                 : "=r"(r0), "=r"(r1), "=r"(r2), "=r"(r3) : "r"(addr));
}
__device__ __forceinline__ uint32_t ldh2(const __half* p) {
    return *(const uint32_t*)p;
}
__device__ __forceinline__ uint32_t h2u(__half2 v) { return *(uint32_t*)&v; }

// ---------------------------------------------------------------------------
// fp16 GEMM (R5 structure + ldmatrix fragment loads):
// C[M,N] = A[M,K] @ W^T + bias, A/W half, W is [N][K] row-major.
// Block 128x128, 128 threads (4 warps, 2x2), warp tile 64x64.
// BK = 64 halfs, 3-stage cp.async pipeline. fp32 accumulate.
// ---------------------------------------------------------------------------
#define GP        72                         // pitch in halfs (144 B)
#define G_AH      (128 * GP)                 // 9216 halfs per A tile
#define G_STAGEH  (2 * G_AH)                 // 18432 halfs (A + B)
#define GEMM_SMEM (3 * G_STAGEH * 2)         // 110592 B

template<bool RELU, bool OUTH>
__global__ void __launch_bounds__(128)
gemm_h(const __half* __restrict__ A, const __half* __restrict__ W,
       const float* __restrict__ bias, void* __restrict__ Cout,
       int M, int N, int K)
{
    extern __shared__ __half sh[];
    const int tid  = threadIdx.x;
    const int warp = tid >> 5, lane = tid & 31;
    const int g = lane >> 2, t = lane & 3;
    const int bm = blockIdx.y * 128;
    const int bn = blockIdx.x * 128;
    const int wm = (warp >> 1) * 64;
    const int wn = (warp &  1) * 64;

    const uint32_t sbase = smem_u32(sh);

    float acc[4][8][4] = {};
    const int KT = K >> 6;   // k-tiles of 64 halfs

    auto fill = [&](int s, int kt) {
        const int k0 = kt << 6;
        const uint32_t st = sbase + (uint32_t)(s * G_STAGEH) * 2;
        #pragma unroll
        for (int i = 0; i < 8; i++) {
            const int idx = tid + i * 128;           // 0..1023
            const int r   = idx >> 3;                // 0..127
            const int kq  = (idx & 7) << 3;          // 0,8,...,56
            cp16(st + (uint32_t)(r * GP + kq) * 2,
                 A + (size_t)(bm + r) * K + k0 + kq);
            cp16(st + (uint32_t)(G_AH + r * GP + kq) * 2,
                 W + (size_t)(bn + r) * K + k0 + kq);
        }
        cp_commit();
    };

    fill(0, 0);
    fill(1, 1);

    for (int kt = 0; kt < KT; kt++) {
        if (kt + 1 < KT) cp_wait1(); else cp_wait0();
        __syncthreads();

        if (kt + 2 < KT) fill((kt + 2) % 3, kt + 2);

        const uint32_t sa = sbase + (uint32_t)((kt % 3) * G_STAGEH) * 2;
        const uint32_t sb = sa + (uint32_t)G_AH * 2;

        #pragma unroll
        for (int kk = 0; kk < 64; kk += 16) {
            uint32_t af[4][4], bf[8][2];
            // A fragments: rows (wm+mt*16 .. +15), k16 block at kk
            #pragma unroll
            for (int mt = 0; mt < 4; mt++) {
                const uint32_t addr = sa +
                    (uint32_t)((wm + mt * 16 + (lane & 15)) * GP +
                               kk + (lane >> 4) * 8) * 2;
                ldsm_x4(af[mt][0], af[mt][1], af[mt][2], af[mt][3], addr);
            }
            // B fragments: 16 n-rows per x4 (two n8 tiles)
            #pragma unroll
            for (int np = 0; np < 4; np++) {
                const uint32_t addr = sb +
                    (uint32_t)((wn + np * 16 + (lane & 7) + ((lane >> 4) << 3)) * GP +
                               kk + ((lane >> 3) & 1) * 8) * 2;
                ldsm_x4(bf[2 * np][0], bf[2 * np][1],
                        bf[2 * np + 1][0], bf[2 * np + 1][1], addr);
            }
            #pragma unroll
            for (int mt = 0; mt < 4; mt++)
                #pragma unroll
                for (int nt = 0; nt < 8; nt++)
                    mma_f16(acc[mt][nt], af[mt][0], af[mt][1], af[mt][2], af[mt][3],
                            bf[nt][0], bf[nt][1]);
        }
        __syncthreads();
    }

    #pragma unroll
    for (int mt = 0; mt < 4; mt++) {
        const int r0 = bm + wm + mt * 16 + g;
        #pragma unroll
        for (int nt = 0; nt < 8; nt++) {
            const int c = bn + wn + nt * 8 + 2 * t;
            float v0 = acc[mt][nt][0] + bias[c];
            float v1 = acc[mt][nt][1] + bias[c + 1];
            float v2 = acc[mt][nt][2] + bias[c];
            float v3 = acc[mt][nt][3] + bias[c + 1];
            if (RELU) {
                v0 = fmaxf(v0, 0.f); v1 = fmaxf(v1, 0.f);
                v2 = fmaxf(v2, 0.f); v3 = fmaxf(v3, 0.f);
            }
            if (OUTH) {
                __half* C = (__half*)Cout;
                *(__half2*)&C[(size_t)r0 * N + c]       = __floats2half2_rn(v0, v1);
                *(__half2*)&C[(size_t)(r0 + 8) * N + c] = __floats2half2_rn(v2, v3);
            } else {
                float* C = (float*)Cout;
                *(float2*)&C[(size_t)r0 * N + c]       = make_float2(v0, v1);
                *(float2*)&C[(size_t)(r0 + 8) * N + c] = make_float2(v2, v3);
            }
        }
    }
}

// ---------------------------------------------------------------------------
// fp32 -> fp16 conversion (vectorized)
// ---------------------------------------------------------------------------
__global__ void __launch_bounds__(256)
f2h_kernel(const float* __restrict__ in, __half* __restrict__ out, int n)
{
    const int i = (blockIdx.x * blockDim.x + threadIdx.x) * 4;
    if (i < n) {
        float4 v = *(const float4*)(in + i);
        *(__half2*)(out + i)     = __floats2half2_rn(v.x, v.y);
        *(__half2*)(out + i + 2) = __floats2half2_rn(v.z, v.w);
    }
}

// ---------------------------------------------------------------------------
// Transpose + convert: out[c][r] = half(in[r][c]), in fp32 [R][Cc]
// ---------------------------------------------------------------------------
__global__ void __launch_bounds__(256)
transpose_h_kernel(const float* __restrict__ in, __half* __restrict__ out,
                   int R, int Cc)
{
    __shared__ float tile[32][33];
    const int c0 = blockIdx.x * 32, r0 = blockIdx.y * 32;
    const int tx = threadIdx.x & 31, ty = threadIdx.x >> 5;   // 32x8
    #pragma unroll
    for (int i = 0; i < 4; i++)
        tile[ty + i * 8][tx] = in[(size_t)(r0 + ty + i * 8) * Cc + c0 + tx];
    __syncthreads();
    #pragma unroll
    for (int i = 0; i < 4; i++)
        out[(size_t)(c0 + ty + i * 8) * R + r0 + tx] =
            __float2half_rn(tile[tx][ty + i * 8]);
}

// ---------------------------------------------------------------------------
// Recurrence: h_t = tanh(h_{t-1} * w_diag + r_t), lane-parallel, half I/O.
// ---------------------------------------------------------------------------
__global__ void recur_kernel(const __half* __restrict__ R,
                             const float* __restrict__ W_h,
                             __half* __restrict__ Hout)
{
    const int gid = blockIdx.x * blockDim.x + threadIdx.x;  // 0..4095
    if (gid >= BATCH * DMODEL) return;
    const int b  = gid >> 9;
    const int hn = gid & 511;

    float w = 0.f;
    const float* wrow = W_h + (size_t)hn * DK;
    #pragma unroll
    for (int k = 0; k < DK; k++) w += wrow[k];

    float hstate = 0.f;
    const size_t stride = (size_t)BATCH * DMODEL;
    size_t idx = (size_t)b * DMODEL + hn;
    #pragma unroll 8
    for (int s = 0; s < SEQ; s++) {
        const float r = __half2float(R[idx]);
        float x = fmaf(hstate, w, r);
        asm("tanh.approx.f32 %0, %1;" : "=f"(hstate) : "f"(x));
        Hout[idx] = __float2half_rn(hstate);
        idx += stride;
    }
}

// ---------------------------------------------------------------------------
// Flash attention (R5-verbatim): fp16 mma, fp32 online softmax.
// 4 warps, q-tile 128 (32 q/warp), key-tile 64.
// Qs/Ks/Ps: [row][d/key] pitch 72; Vt: [d][key] pitch 72 (transposed at stage).
// scores = (Q.K)*0.125 + (k>q ? 1.0 : 0.0)
// ---------------------------------------------------------------------------
#define AP       72
#define QS_OFF   0
#define KS_OFF   (128 * AP)
#define VT_OFF   (KS_OFF + 64 * AP)
#define PS_OFF   (VT_OFF + 64 * AP)
#define ATTN_SMEM ((PS_OFF + 128 * AP) * 2)   // 55296 B

__global__ void __launch_bounds__(128)
attn_h(const __half* __restrict__ Q, const __half* __restrict__ Hk,
       const __half* __restrict__ V, __half* __restrict__ O)
{
    extern __shared__ __half sh[];
    __half (*Qs)[AP] = (__half(*)[AP])(sh + QS_OFF);
    __half (*Ks)[AP] = (__half(*)[AP])(sh + KS_OFF);
    __half (*Vt)[AP] = (__half(*)[AP])(sh + VT_OFF);
    __half (*Ps)[AP] = (__half(*)[AP])(sh + PS_OFF);

    const int tid  = threadIdx.x;
    const int warp = tid >> 5, lane = tid & 31;
    const int g = lane >> 2, t = lane & 3;
    const int bh = blockIdx.y;
    const int b  = bh >> 3, h = bh & 7;
    const int q0 = blockIdx.x << 7;          // 128 q rows per block

    // ---- stage Q tile (128 rows x 64 halfs) ----
    #pragma unroll
    for (int i = 0; i < 8; i++) {
        const int idx = tid + i * 128;       // 0..1023 8-half chunks
        const int r   = idx >> 3;            // 0..127
        const int dq  = (idx & 7) * 8;       // 0..56
        const size_t ga = ((size_t)(q0 + r) * BATCH + b) * DMODEL + h * DK + dq;
        *(float4*)&Qs[r][dq] = *(const float4*)&Q[ga];
    }

    float o[2][8][4] = {};
    float mrow[4] = {-1e30f, -1e30f, -1e30f, -1e30f};
    float lrow[4] = {0.f, 0.f, 0.f, 0.f};
    const float scale = 0.125f;

    __syncthreads();

    for (int k0 = 0; k0 < SEQ; k0 += 64) {
        // ---- stage K tile + V tile (transposed) ----
        #pragma unroll
        for (int i = 0; i < 4; i++) {
            const int idx = tid + i * 128;   // 0..511
            const int r   = idx >> 3;        // 0..63 (key)
            const int dq  = (idx & 7) * 8;   // 0..56
            const size_t ga = ((size_t)(k0 + r) * BATCH + b) * DMODEL + h * DK + dq;
            *(float4*)&Ks[r][dq] = *(const float4*)&Hk[ga];
            const __half* vp = &V[ga];
            #pragma unroll
            for (int j = 0; j < 8; j++)
                Vt[dq + j][r] = vp[j];
        }
        __syncthreads();

        #pragma unroll
        for (int mt = 0; mt < 2; mt++) {
            const int qrow = warp * 32 + mt * 16;

            // ---- S = Q @ K^T  (16q x 64k, d=64 in 4 k16 steps) ----
            float s[8][4] = {};
            #pragma unroll
            for (int kk = 0; kk < 64; kk += 16) {
                const uint32_t a0 = ldh2(&Qs[qrow + g    ][kk + 2 * t    ]);
                const uint32_t a1 = ldh2(&Qs[qrow + 8 + g][kk + 2 * t    ]);
                const uint32_t a2 = ldh2(&Qs[qrow + g    ][kk + 2 * t + 8]);
                const uint32_t a3 = ldh2(&Qs[qrow + 8 + g][kk + 2 * t + 8]);
                #pragma unroll
                for (int nt = 0; nt < 8; nt++) {
                    const uint32_t b0 = ldh2(&Ks[nt * 8 + g][kk + 2 * t    ]);
                    const uint32_t b1 = ldh2(&Ks[nt * 8 + g][kk + 2 * t + 8]);
                    mma_f16(s[nt], a0, a1, a2, a3, b0, b1);
                }
            }

            // ---- scale + mask ----
            const int qg0 = q0 + qrow + g;
            #pragma unroll
            for (int nt = 0; nt < 8; nt++) {
                const int kg = k0 + nt * 8 + 2 * t;
                s[nt][0] = s[nt][0] * scale + ((kg     > qg0    ) ? 1.f : 0.f);
                s[nt][1] = s[nt][1] * scale + ((kg + 1 > qg0    ) ? 1.f : 0.f);
                s[nt][2] = s[nt][2] * scale + ((kg     > qg0 + 8) ? 1.f : 0.f);
                s[nt][3] = s[nt][3] * scale + ((kg + 1 > qg0 + 8) ? 1.f : 0.f);
            }

            // ---- online softmax (rows g, g+8) ----
            #pragma unroll
            for (int half_i = 0; half_i < 2; half_i++) {
                const int ri = mt * 2 + half_i;
                float tm = -1e30f;
                #pragma unroll
                for (int nt = 0; nt < 8; nt++) {
                    tm = fmaxf(tm, s[nt][2 * half_i]);
                    tm = fmaxf(tm, s[nt][2 * half_i + 1]);
                }
                tm = fmaxf(tm, __shfl_xor_sync(0xffffffffu, tm, 1));
                tm = fmaxf(tm, __shfl_xor_sync(0xffffffffu, tm, 2));
                const float mnew = fmaxf(mrow[ri], tm);
                const float corr = __expf(mrow[ri] - mnew);
                float ts = 0.f;
                #pragma unroll
                for (int nt = 0; nt < 8; nt++) {
                    s[nt][2 * half_i]     = __expf(s[nt][2 * half_i]     - mnew);
                    s[nt][2 * half_i + 1] = __expf(s[nt][2 * half_i + 1] - mnew);
                    ts += s[nt][2 * half_i] + s[nt][2 * half_i + 1];
                }
                ts += __shfl_xor_sync(0xffffffffu, ts, 1);
                ts += __shfl_xor_sync(0xffffffffu, ts, 2);
                lrow[ri] = lrow[ri] * corr + ts;
                mrow[ri] = mnew;
                #pragma unroll
                for (int nt = 0; nt < 8; nt++) {
                    o[mt][nt][2 * half_i]     *= corr;
                    o[mt][nt][2 * half_i + 1] *= corr;
                }
            }

            // ---- write P (half) ----
            #pragma unroll
            for (int nt = 0; nt < 8; nt++) {
                const int c = nt * 8 + 2 * t;
                *(__half2*)&Ps[qrow + g    ][c] = __floats2half2_rn(s[nt][0], s[nt][1]);
                *(__half2*)&Ps[qrow + 8 + g][c] = __floats2half2_rn(s[nt][2], s[nt][3]);
            }
            __syncwarp();

            // ---- O += P @ V  (64 keys in 4 k16 steps) ----
            #pragma unroll
            for (int kb = 0; kb < 64; kb += 16) {
                const uint32_t a0 = ldh2(&Ps[qrow + g    ][kb + 2 * t    ]);
                const uint32_t a1 = ldh2(&Ps[qrow + 8 + g][kb + 2 * t    ]);
                const uint32_t a2 = ldh2(&Ps[qrow + g    ][kb + 2 * t + 8]);
                const uint32_t a3 = ldh2(&Ps[qrow + 8 + g][kb + 2 * t + 8]);
                #pragma unroll
                for (int nt = 0; nt < 8; nt++) {
                    const uint32_t b0 = ldh2(&Vt[nt * 8 + g][kb + 2 * t    ]);
                    const uint32_t b1 = ldh2(&Vt[nt * 8 + g][kb + 2 * t + 8]);
                    mma_f16(o[mt][nt], a0, a1, a2, a3, b0, b1);
                }
            }
        }
        __syncthreads();   // protect Ks/Vt for next tile
    }

    // ---- epilogue: normalize & store half ----
    #pragma unroll
    for (int mt = 0; mt < 2; mt++) {
        const float inv0 = 1.f / lrow[mt * 2];
        const float inv1 = 1.f / lrow[mt * 2 + 1];
        const int r0 = q0 + warp * 32 + mt * 16 + g;
        #pragma unroll
        for (int nt = 0; nt < 8; nt++) {
            const int c = h * DK + nt * 8 + 2 * t;
            *(__half2*)&O[((size_t)r0 * BATCH + b) * DMODEL + c] =
                __floats2half2_rn(o[mt][nt][0] * inv0, o[mt][nt][1] * inv0);
            *(__half2*)&O[((size_t)(r0 + 8) * BATCH + b) * DMODEL + c] =
                __floats2half2_rn(o[mt][nt][2] * inv1, o[mt][nt][3] * inv1);
        }
    }
}

// ---------------------------------------------------------------------------
// Fused residual-add + LayerNorm; optional half copy of the output.
// ---------------------------------------------------------------------------
__global__ void __launch_bounds__(256)
add_ln_kernel(const float* __restrict__ X, const float* __restrict__ Y,
              const float* __restrict__ gamma, const float* __restrict__ beta,
              float* __restrict__ out, __half* __restrict__ outh)
{
    const int warp = (blockIdx.x * blockDim.x + threadIdx.x) >> 5;
    const int lane = threadIdx.x & 31;
    if (warp >= TTOK) return;

    const float* xr = X + (size_t)warp * DMODEL;
    const float* yr = Y + (size_t)warp * DMODEL;

    float v[16];
    float sum = 0.f;
    #pragma unroll
    for (int i = 0; i < 16; i++) {
        v[i] = xr[lane + i * 32] + yr[lane + i * 32];
        sum += v[i];
    }
    #pragma unroll
    for (int m = 16; m > 0; m >>= 1) sum += __shfl_xor_sync(0xffffffffu, sum, m);
    const float mu = sum * (1.f / DMODEL);

    float var = 0.f;
    #pragma unroll
    for (int i = 0; i < 16; i++) { const float d = v[i] - mu; var = fmaf(d, d, var); }
    #pragma unroll
    for (int m = 16; m > 0; m >>= 1) var += __shfl_xor_sync(0xffffffffu, var, m);
    const float rstd = rsqrtf(var * (1.f / DMODEL) + 1e-5f);

    float* orow = out + (size_t)warp * DMODEL;
    #pragma unroll
    for (int i = 0; i < 16; i++) {
        const int c = lane + i * 32;
        const float val = (v[i] - mu) * rstd * gamma[c] + beta[c];
        orow[c] = val;
        if (outh) outh[(size_t)warp * DMODEL + c] = __float2half_rn(val);
    }
}

// ---------------------------------------------------------------------------
// Launch orchestration
// ---------------------------------------------------------------------------
extern "C" void kernel_launch(void* const* d_in, const int* in_sizes, int n_in,
                              void* d_out, int out_size)
{
    const float* x     = (const float*)d_in[0];
    const float* Wq    = (const float*)d_in[1];
    const float* bq    = (const float*)d_in[2];
    const float* Wv    = (const float*)d_in[3];
    const float* bv    = (const float*)d_in[4];
    const float* Wr    = (const float*)d_in[5];
    const float* br    = (const float*)d_in[6];
    const float* W_h   = (const float*)d_in[7];
    const float* Wo    = (const float*)d_in[8];
    const float* bo    = (const float*)d_in[9];
    const float* ln1_g = (const float*)d_in[10];
    const float* ln1_b = (const float*)d_in[11];
    const float* Wf1   = (const float*)d_in[12];
    const float* bf1   = (const float*)d_in[13];
    const float* Wf2   = (const float*)d_in[14];
    const float* bf2   = (const float*)d_in[15];
    const float* ln2_g = (const float*)d_in[16];
    const float* ln2_b = (const float*)d_in[17];
    float* out = (float*)d_out;

    static __half *pxh = nullptr, *pQh, *pVh, *pRh, *pHh, *pAh, *px1h, *pFFh,
                  *pWqh, *pWvh, *pWrh, *pWoh, *pW1T, *pW2T;
    static float *pTmp, *pX1;
    if (!pxh) {
        cudaGetSymbolAddress((void**)&pxh,  g_xh);
        cudaGetSymbolAddress((void**)&pQh,  g_Qh);
        cudaGetSymbolAddress((void**)&pVh,  g_Vh);
        cudaGetSymbolAddress((void**)&pRh,  g_Rh);
        cudaGetSymbolAddress((void**)&pHh,  g_Hh);
        cudaGetSymbolAddress((void**)&pAh,  g_attnh);
        cudaGetSymbolAddress((void**)&px1h, g_x1h);
        cudaGetSymbolAddress((void**)&pFFh, g_ffh);
        cudaGetSymbolAddress((void**)&pWqh, g_Wqh);
        cudaGetSymbolAddress((void**)&pWvh, g_Wvh);
        cudaGetSymbolAddress((void**)&pWrh, g_Wrh);
        cudaGetSymbolAddress((void**)&pWoh, g_Woh);
        cudaGetSymbolAddress((void**)&pW1T, g_Wf1T);
        cudaGetSymbolAddress((void**)&pW2T, g_Wf2T);
        cudaGetSymbolAddress((void**)&pTmp, g_tmp);
        cudaGetSymbolAddress((void**)&pX1,  g_x1);
        cudaFuncSetAttribute(attn_h, cudaFuncAttributeMaxDynamicSharedMemorySize,
                             ATTN_SMEM);
        cudaFuncSetAttribute(gemm_h<false, true>,
                             cudaFuncAttributeMaxDynamicSharedMemorySize, GEMM_SMEM);
        cudaFuncSetAttribute(gemm_h<false, false>,
                             cudaFuncAttributeMaxDynamicSharedMemorySize, GEMM_SMEM);
        cudaFuncSetAttribute(gemm_h<true, true>,
                             cudaFuncAttributeMaxDynamicSharedMemorySize, GEMM_SMEM);
    }

    const dim3 gP (DMODEL / 128, TTOK / 128);   // (4, 128)
    const dim3 gF1(DFF    / 128, TTOK / 128);   // (16, 128)
    const dim3 gAt(SEQ / 128, BATCH * HEADS);   // (16, 64)
    const dim3 gLN(TTOK / 8, 1);

    // 0) conversions
    f2h_kernel<<<(TTOK * DMODEL / 4 + 255) / 256, 256>>>(x, pxh, TTOK * DMODEL);
    f2h_kernel<<<(DMODEL * DMODEL / 4 + 255) / 256, 256>>>(Wq, pWqh, DMODEL * DMODEL);
    f2h_kernel<<<(DMODEL * DMODEL / 4 + 255) / 256, 256>>>(Wv, pWvh, DMODEL * DMODEL);
    f2h_kernel<<<(DMODEL * DMODEL / 4 + 255) / 256, 256>>>(Wr, pWrh, DMODEL * DMODEL);
    f2h_kernel<<<(DMODEL * DMODEL / 4 + 255) / 256, 256>>>(Wo, pWoh, DMODEL * DMODEL);
    transpose_h_kernel<<<dim3(DFF / 32, DMODEL / 32), 256>>>(Wf1, pW1T, DMODEL, DFF);
    transpose_h_kernel<<<dim3(DMODEL / 32, DFF / 32), 256>>>(Wf2, pW2T, DFF, DMODEL);

    // 1) Q, V, R projections (half out)
    gemm_h<false, true><<<gP, 128, GEMM_SMEM>>>(pxh, pWqh, bq, pQh, TTOK, DMODEL, DMODEL);
    gemm_h<false, true><<<gP, 128, GEMM_SMEM>>>(pxh, pWvh, bv, pVh, TTOK, DMODEL, DMODEL);
    gemm_h<false, true><<<gP, 128, GEMM_SMEM>>>(pxh, pWrh, br, pRh, TTOK, DMODEL, DMODEL);

    // 2) recurrence -> keys H
    recur_kernel<<<16, 256>>>(pRh, W_h, pHh);

    // 3) attention (half in/out)
    attn_h<<<gAt, 128, ATTN_SMEM>>>(pQh, pHh, pVh, pAh);

    // 4) output projection (fp32 out, feeds LN)
    gemm_h<false, false><<<gP, 128, GEMM_SMEM>>>(pAh, pWoh, bo, pTmp, TTOK, DMODEL, DMODEL);

    // 5) x1 = LN1(x + attn_proj): fp32 + half copies
    add_ln_kernel<<<gLN, 256>>>(x, pTmp, ln1_g, ln1_b, pX1, px1h);

    // 6) ff = relu(x1 @ Wf1 + bf1) (half out)
    gemm_h<true, true><<<gF1, 128, GEMM_SMEM>>>(px1h, pW1T, bf1, pFFh, TTOK, DFF, DMODEL);

    // 7) ff2 = ff @ Wf2 + bf2 (fp32 out, feeds LN)
    gemm_h<false, false><<<gP, 128, GEMM_SMEM>>>(pFFh, pW2T, bf2, pTmp, TTOK, DMODEL, DFF);

    // 8) out = LN2(x1 + ff2)
    add_ln_kernel<<<gLN, 256>>>(pX1, pTmp, ln2_g, ln2_b, out, nullptr);
}